// round 4
// baseline (speedup 1.0000x reference)
#include <cuda_runtime.h>
#include <cuda_bf16.h>
#include <math.h>
#include <stdint.h>

// Problem constants (fixed by the dataset)
#define N_SPOTS   100000
#define N_GENES   512
#define N_SPH     511
#define N_EDGES   600000
#define N_NEI     6
#define SCAN_B    ((N_SPOTS + 1023) / 1024)   // 98

// ---------------- scratch (device globals) ----------------------------------
__device__ float g_gex[(size_t)N_SPOTS * N_GENES];   // 204.8 MB
__device__ float g_x  [(size_t)N_SPOTS * N_GENES];   // 204.8 MB
__device__ int   g_cnt[N_SPOTS];
__device__ int   g_off[N_SPOTS + 1];
__device__ int   g_cur[N_SPOTS];
__device__ int   g_ebuf[N_EDGES];
__device__ int   g_bsum[SCAN_B];
__device__ float g_dinv[N_SPOTS];
__device__ float g_colsum[N_GENES];

// ---------------- init ------------------------------------------------------
__global__ void k_zero(void) {
    int i = blockIdx.x * blockDim.x + threadIdx.x;
    if (i < N_SPOTS) g_cnt[i] = 0;
    if (i < N_GENES) g_colsum[i] = 0.0f;
}

// ---------------- gex: warp-per-row product scan ----------------------------
__global__ void k_gex(const float* __restrict__ sphex) {
    int gwarp = (blockIdx.x * blockDim.x + threadIdx.x) >> 5;
    int lane  = threadIdx.x & 31;
    if (gwarp >= N_SPOTS) return;
    const float* row = sphex + (size_t)gwarp * N_SPH;
    float* orow = g_gex + (size_t)gwarp * N_GENES;

    float P = 1.0f;
    for (int base = 0; base < N_SPH; base += 32) {
        int idx = base + lane;
        float s = 1.0f, c = 1.0f;
        if (idx < N_SPH) {
            float xv = row[idx];
            sincosf(xv, &s, &c);
        }
        float incl = s;
        #pragma unroll
        for (int off = 1; off < 32; off <<= 1) {
            float o = __shfl_up_sync(0xffffffffu, incl, off);
            if (lane >= off) incl *= o;
        }
        float excl = __shfl_up_sync(0xffffffffu, incl, 1);
        if (lane == 0) excl = 1.0f;
        if (idx < N_SPH) orow[idx] = P * excl * c;
        P *= __shfl_sync(0xffffffffu, incl, 31);
    }
    if (lane == 0) orow[N_SPH] = P;
}

// ---------------- fused dual TF32 GEMM --------------------------------------
// C1[m,o] = sum_k A[m,k] Wc[o,k];  C2[m,o] = sum_k A[m,k] Wl[o,k] + bl[o]
#define BK 32
#define TS 36      // smem row stride (floats)

__device__ __forceinline__ float to_tf32(float x) {
    float r;
    asm("cvt.rna.tf32.f32 %0, %1;" : "=f"(r) : "f"(x));
    return r;
}

__device__ __forceinline__ void mma_tf32(float* c, const float* a, const float* b) {
    const uint32_t* A = reinterpret_cast<const uint32_t*>(a);
    const uint32_t* B = reinterpret_cast<const uint32_t*>(b);
    asm volatile(
        "mma.sync.aligned.m16n8k8.row.col.f32.tf32.tf32.f32 "
        "{%0,%1,%2,%3}, {%4,%5,%6,%7}, {%8,%9}, {%0,%1,%2,%3};"
        : "+f"(c[0]), "+f"(c[1]), "+f"(c[2]), "+f"(c[3])
        : "r"(A[0]), "r"(A[1]), "r"(A[2]), "r"(A[3]), "r"(B[0]), "r"(B[1]));
}

__global__ void __launch_bounds__(256)
k_mma_dual(const float* __restrict__ A, const float* __restrict__ Wc,
           const float* __restrict__ Wl, const float* __restrict__ bl,
           float* __restrict__ C1, float* __restrict__ C2, int M) {
    const int K = N_GENES;
    extern __shared__ float sm[];
    float* As = sm;                    // 128 x TS
    float* Bc = sm + 128 * TS;
    float* Bl = sm + 2 * 128 * TS;

    int tid  = threadIdx.x;
    int warp = tid >> 5;
    int lane = tid & 31;
    int wm = warp >> 2;           // 0..1
    int wn = warp & 3;            // 0..3
    int n0 = blockIdx.x * 128;
    int m0 = blockIdx.y * 128;
    int gq = lane >> 2;           // 0..7
    int gr = lane & 3;            // 0..3

    float accC[4][4][4], accL[4][4][4];
    #pragma unroll
    for (int i = 0; i < 4; i++)
        #pragma unroll
        for (int j = 0; j < 4; j++)
            #pragma unroll
            for (int r = 0; r < 4; r++) { accC[i][j][r] = 0.0f; accL[i][j][r] = 0.0f; }

    for (int kt = 0; kt < K; kt += BK) {
        #pragma unroll
        for (int j = 0; j < 4; j++) {
            int i = tid + 256 * j;         // 1024 float4 slots per matrix
            int row = i >> 3;
            int c4  = (i & 7) * 4;
            int m = m0 + row;
            float4 av = (m < M) ? *(const float4*)(A + (size_t)m * K + kt + c4)
                                : make_float4(0.f, 0.f, 0.f, 0.f);
            float4 cv = *(const float4*)(Wc + (size_t)(n0 + row) * K + kt + c4);
            float4 lv = *(const float4*)(Wl + (size_t)(n0 + row) * K + kt + c4);
            av.x = to_tf32(av.x); av.y = to_tf32(av.y);
            av.z = to_tf32(av.z); av.w = to_tf32(av.w);
            cv.x = to_tf32(cv.x); cv.y = to_tf32(cv.y);
            cv.z = to_tf32(cv.z); cv.w = to_tf32(cv.w);
            lv.x = to_tf32(lv.x); lv.y = to_tf32(lv.y);
            lv.z = to_tf32(lv.z); lv.w = to_tf32(lv.w);
            *(float4*)&As[row * TS + c4] = av;
            *(float4*)&Bc[row * TS + c4] = cv;
            *(float4*)&Bl[row * TS + c4] = lv;
        }
        __syncthreads();

        #pragma unroll
        for (int s = 0; s < 4; s++) {
            int k0 = s * 8 + gr;
            int k1 = k0 + 4;
            float af[4][4], bcf[4][2], blf[4][2];
            #pragma unroll
            for (int mf = 0; mf < 4; mf++) {
                int r0 = wm * 64 + mf * 16 + gq;
                af[mf][0] = As[r0 * TS + k0];
                af[mf][1] = As[(r0 + 8) * TS + k0];
                af[mf][2] = As[r0 * TS + k1];
                af[mf][3] = As[(r0 + 8) * TS + k1];
            }
            #pragma unroll
            for (int nf = 0; nf < 4; nf++) {
                int cN = wn * 32 + nf * 8 + gq;
                bcf[nf][0] = Bc[cN * TS + k0];
                bcf[nf][1] = Bc[cN * TS + k1];
                blf[nf][0] = Bl[cN * TS + k0];
                blf[nf][1] = Bl[cN * TS + k1];
            }
            #pragma unroll
            for (int mf = 0; mf < 4; mf++)
                #pragma unroll
                for (int nf = 0; nf < 4; nf++) {
                    mma_tf32(accC[mf][nf], af[mf], bcf[nf]);
                    mma_tf32(accL[mf][nf], af[mf], blf[nf]);
                }
        }
        __syncthreads();
    }

    // epilogue
    #pragma unroll
    for (int mf = 0; mf < 4; mf++) {
        int r0 = m0 + wm * 64 + mf * 16 + gq;
        #pragma unroll
        for (int nf = 0; nf < 4; nf++) {
            int cN = n0 + wn * 32 + nf * 8 + gr * 2;
            float b0 = bl[cN];
            float b1 = bl[cN + 1];
            if (r0 < M) {
                *(float2*)(C1 + (size_t)r0 * K + cN) =
                    make_float2(accC[mf][nf][0], accC[mf][nf][1]);
                *(float2*)(C2 + (size_t)r0 * K + cN) =
                    make_float2(accL[mf][nf][0] + b0, accL[mf][nf][1] + b1);
            }
            if (r0 + 8 < M) {
                *(float2*)(C1 + (size_t)(r0 + 8) * K + cN) =
                    make_float2(accC[mf][nf][2], accC[mf][nf][3]);
                *(float2*)(C2 + (size_t)(r0 + 8) * K + cN) =
                    make_float2(accL[mf][nf][2] + b0, accL[mf][nf][3] + b1);
            }
        }
    }
}

// ---------------- CSR build: count, scan, bucket ----------------------------
__global__ void k_cnt(const int* __restrict__ dst) {
    int e = blockIdx.x * blockDim.x + threadIdx.x;
    if (e < N_EDGES) atomicAdd(&g_cnt[dst[e]], 1);
}

__global__ void k_scan1(void) {
    __shared__ int s[1024];
    int t = threadIdx.x;
    int i = blockIdx.x * 1024 + t;
    int v = (i < N_SPOTS) ? g_cnt[i] : 0;
    s[t] = v;
    __syncthreads();
    for (int off = 1; off < 1024; off <<= 1) {
        int a = (t >= off) ? s[t - off] : 0;
        __syncthreads();
        s[t] += a;
        __syncthreads();
    }
    if (i < N_SPOTS) g_off[i] = s[t] - v;           // local exclusive
    if (t == 1023) g_bsum[blockIdx.x] = s[1023];    // block total
}

__global__ void k_scan2(void) {
    __shared__ int s[128];
    int t = threadIdx.x;
    int v = (t < SCAN_B) ? g_bsum[t] : 0;
    s[t] = v;
    __syncthreads();
    for (int off = 1; off < 128; off <<= 1) {
        int a = (t >= off) ? s[t - off] : 0;
        __syncthreads();
        s[t] += a;
        __syncthreads();
    }
    if (t < SCAN_B) g_bsum[t] = s[t] - v;           // exclusive block offsets
}

__global__ void k_scan3(void) {
    int i = blockIdx.x * blockDim.x + threadIdx.x;
    if (i < N_SPOTS) {
        int off = g_off[i] + g_bsum[i >> 10];
        g_off[i] = off;
        g_cur[i] = off;
        int c = g_cnt[i];
        g_dinv[i] = (c > 0) ? rsqrtf((float)c) : 0.0f;
    }
    if (i == 0) g_off[N_SPOTS] = N_EDGES;
}

__global__ void k_bucket(const int* __restrict__ src, const int* __restrict__ dst) {
    int e = blockIdx.x * blockDim.x + threadIdx.x;
    if (e < N_EDGES) {
        int pos = atomicAdd(&g_cur[dst[e]], 1);
        g_ebuf[pos] = src[e];
    }
}

// ---------------- gather: msg[d] = bc + sum_{src in bucket(d)} norm * x[src]
__global__ void k_gather(const float* __restrict__ bc, float* __restrict__ msg) {
    int d = blockIdx.x;
    int t = threadIdx.x;            // 0..127
    int beg = g_off[d], end = g_off[d + 1];
    float di = g_dinv[d];
    float4 acc = ((const float4*)bc)[t];
    for (int i = beg; i < end; i++) {
        int s = g_ebuf[i];
        float nrm = di * g_dinv[s];
        float4 v = ((const float4*)(g_x + (size_t)s * N_GENES))[t];
        acc.x = fmaf(nrm, v.x, acc.x);
        acc.y = fmaf(nrm, v.y, acc.y);
        acc.z = fmaf(nrm, v.z, acc.z);
        acc.w = fmaf(nrm, v.w, acc.w);
    }
    ((float4*)(msg + (size_t)d * N_GENES))[t] = acc;
}

// ---------------- column sums of gex ----------------------------------------
__global__ void k_colsum(void) {
    __shared__ float s[N_GENES];
    int t = threadIdx.x;
    s[t] = 0.0f; s[t + 256] = 0.0f;
    __syncthreads();
    for (int r = blockIdx.x; r < N_SPOTS; r += gridDim.x) {
        const float* row = g_gex + (size_t)r * N_GENES;
        s[t]       += row[t];
        s[t + 256] += row[t + 256];
    }
    __syncthreads();
    atomicAdd(&g_colsum[t], s[t]);
    atomicAdd(&g_colsum[t + 256], s[t + 256]);
}

// ---------------- mean-field scalar ----------------------------------------
__global__ void k_finalize(const float* __restrict__ Wc, const float* __restrict__ Wl,
                           float* __restrict__ out_scalar) {
    __shared__ float mean[N_GENES];
    __shared__ float red[N_GENES];
    int t = threadIdx.x;   // 512 threads
    mean[t] = g_colsum[t] * (1.0f / (float)N_SPOTS);
    __syncthreads();

    float v = 0.0f, u = 0.0f;
    const float* wc = Wc + (size_t)t * N_GENES;
    const float* wl = Wl + (size_t)t * N_GENES;
    for (int k = 0; k < N_GENES; k++) {
        float m = mean[k];
        v = fmaf((float)N_NEI * wc[k] + 2.0f * wl[k], m, v);
        u = fmaf(wl[k] + 0.5f * (float)N_NEI * wc[k], m, u);
    }

    red[t] = v * v;
    __syncthreads();
    for (int s = 256; s > 0; s >>= 1) {
        if (t < s) red[t] += red[t + s];
        __syncthreads();
    }
    float g2 = red[0];
    __syncthreads();

    red[t] = mean[t] * u;
    __syncthreads();
    for (int s = 256; s > 0; s >>= 1) {
        if (t < s) red[t] += red[t + s];
        __syncthreads();
    }
    if (t == 0) {
        float g = sqrtf(g2);
        float z_mean = -(float)N_SPOTS * red[0];
        float gc = fminf(g, 20.0f);
        float z_int;
        if (g > 20.0f)
            z_int = (float)N_SPOTS * (g - logf(g));
        else
            z_int = (float)N_SPOTS * logf((expf(gc) - expf(-gc)) / gc);
        out_scalar[0] = z_mean + z_int;
    }
}

// ---------------- launch ----------------------------------------------------
extern "C" void kernel_launch(void* const* d_in, const int* in_sizes, int n_in,
                              void* d_out, int out_size) {
    const float* sphex = (const float*)d_in[0];   // [100000, 511]
    const float* Wc    = (const float*)d_in[1];   // [512, 512]
    const float* bc    = (const float*)d_in[2];   // [512]
    const float* Wl    = (const float*)d_in[3];   // [512, 512]
    const float* bl    = (const float*)d_in[4];   // [512]
    const int*   eidx  = (const int*)d_in[5];     // [2, 600000]
    (void)in_sizes; (void)n_in; (void)out_size;

    const int* e_src = eidx;
    const int* e_dst = eidx + N_EDGES;

    float* out       = (float*)d_out;
    float* out_msg   = out;                                  // [N, G]
    float* out_intra = out + (size_t)N_SPOTS * N_GENES;      // [N, G]
    float* out_logz  = out + 2 * (size_t)N_SPOTS * N_GENES;  // [1]

    float *p_gex, *p_x;
    cudaGetSymbolAddress((void**)&p_gex, g_gex);
    cudaGetSymbolAddress((void**)&p_x,   g_x);

    // 0) zero counters
    k_zero<<<(N_SPOTS + 255) / 256, 256>>>();

    // 1) CSR build (independent of gex/GEMM)
    k_cnt<<<(N_EDGES + 255) / 256, 256>>>(e_dst);
    k_scan1<<<SCAN_B, 1024>>>();
    k_scan2<<<1, 128>>>();
    k_scan3<<<(N_SPOTS + 255) / 256, 256>>>();
    k_bucket<<<(N_EDGES + 255) / 256, 256>>>(e_src, e_dst);

    // 2) gex (warp per row)
    k_gex<<<(N_SPOTS * 32 + 255) / 256, 256>>>(sphex);

    // 3) fused dual GEMM (tf32 tensor cores)
    {
        static const int smem_bytes = 3 * 128 * TS * sizeof(float);  // 55296
        cudaFuncSetAttribute(k_mma_dual, cudaFuncAttributeMaxDynamicSharedMemorySize,
                             smem_bytes);
        dim3 grid(N_GENES / 128, (N_SPOTS + 127) / 128);
        k_mma_dual<<<grid, 256, smem_bytes>>>(p_gex, Wc, Wl, bl, p_x, out_intra, N_SPOTS);
    }

    // 4) gather per destination (bias folded in, no atomics)
    k_gather<<<N_SPOTS, 128>>>(bc, out_msg);

    // 5) column sums -> mean -> scalar
    k_colsum<<<512, 256>>>();
    k_finalize<<<1, 512>>>(Wc, Wl, out_logz);
}

// round 6
// speedup vs baseline: 1.4766x; 1.4766x over previous
#include <cuda_runtime.h>
#include <cuda_bf16.h>
#include <math.h>
#include <stdint.h>

// Problem constants (fixed by the dataset)
#define N_SPOTS   100000
#define N_GENES   512
#define N_SPH     511
#define N_EDGES   600000
#define N_NEI     6
#define SCAN_B    ((N_SPOTS + 1023) / 1024)   // 98

// ---------------- scratch (device globals) ----------------------------------
__device__ float g_gex[(size_t)N_SPOTS * N_GENES];   // 204.8 MB (tf32-rounded)
__device__ float g_x  [(size_t)N_SPOTS * N_GENES];   // 204.8 MB
__device__ float g_wc [N_GENES * N_GENES];           // tf32-rounded Wc
__device__ float g_wl [N_GENES * N_GENES];           // tf32-rounded Wl
__device__ int   g_cnt[N_SPOTS];
__device__ int   g_off[N_SPOTS + 1];
__device__ int   g_cur[N_SPOTS];
__device__ int   g_ebuf[N_EDGES];
__device__ int   g_bsum[SCAN_B];
__device__ float g_dinv[N_SPOTS];
__device__ float g_colsum[N_GENES];

__device__ __forceinline__ float to_tf32(float x) {
    float r;
    asm("cvt.rna.tf32.f32 %0, %1;" : "=f"(r) : "f"(x));
    return r;
}

// ---------------- init ------------------------------------------------------
__global__ void k_zero(void) {
    int i = blockIdx.x * blockDim.x + threadIdx.x;
    if (i < N_SPOTS) g_cnt[i] = 0;
    if (i < N_GENES) g_colsum[i] = 0.0f;
}

// ---------------- weight pre-round to tf32 ----------------------------------
__global__ void k_cvtW(const float* __restrict__ Wc, const float* __restrict__ Wl) {
    int i = blockIdx.x * blockDim.x + threadIdx.x;   // 262144
    g_wc[i] = to_tf32(Wc[i]);
    g_wl[i] = to_tf32(Wl[i]);
}

// ---------------- gex: warp-per-row product scan (stores tf32-rounded) ------
__global__ void k_gex(const float* __restrict__ sphex) {
    int gwarp = (blockIdx.x * blockDim.x + threadIdx.x) >> 5;
    int lane  = threadIdx.x & 31;
    if (gwarp >= N_SPOTS) return;
    const float* row = sphex + (size_t)gwarp * N_SPH;
    float* orow = g_gex + (size_t)gwarp * N_GENES;

    float P = 1.0f;
    for (int base = 0; base < N_SPH; base += 32) {
        int idx = base + lane;
        float s = 1.0f, c = 1.0f;
        if (idx < N_SPH) {
            float xv = row[idx];
            sincosf(xv, &s, &c);
        }
        float incl = s;
        #pragma unroll
        for (int off = 1; off < 32; off <<= 1) {
            float o = __shfl_up_sync(0xffffffffu, incl, off);
            if (lane >= off) incl *= o;
        }
        float excl = __shfl_up_sync(0xffffffffu, incl, 1);
        if (lane == 0) excl = 1.0f;
        if (idx < N_SPH) orow[idx] = to_tf32(P * excl * c);
        P *= __shfl_sync(0xffffffffu, incl, 31);
    }
    if (lane == 0) orow[N_SPH] = to_tf32(P);
}

// ---------------- TF32 tensor GEMM with cp.async double buffering -----------
// C[m,o] = sum_k A[m,k] * W[o,k] (+ bias[o]); A,W already tf32-rounded.
#define BK 32
#define TS 36      // smem row stride (floats)

__device__ __forceinline__ uint32_t smem_u32(const void* p) {
    return (uint32_t)__cvta_generic_to_shared(p);
}
__device__ __forceinline__ void cp16(uint32_t dst, const void* src, bool pred) {
    int sz = pred ? 16 : 0;
    asm volatile("cp.async.ca.shared.global [%0], [%1], 16, %2;"
                 :: "r"(dst), "l"(src), "r"(sz));
}

__device__ __forceinline__ void mma_tf32(float* c, const float* a, const float* b) {
    const uint32_t* A = reinterpret_cast<const uint32_t*>(a);
    const uint32_t* B = reinterpret_cast<const uint32_t*>(b);
    asm volatile(
        "mma.sync.aligned.m16n8k8.row.col.f32.tf32.tf32.f32 "
        "{%0,%1,%2,%3}, {%4,%5,%6,%7}, {%8,%9}, {%0,%1,%2,%3};"
        : "+f"(c[0]), "+f"(c[1]), "+f"(c[2]), "+f"(c[3])
        : "r"(A[0]), "r"(A[1]), "r"(A[2]), "r"(A[3]), "r"(B[0]), "r"(B[1]));
}

template <bool ADD_BIAS>
__global__ void __launch_bounds__(256, 2)
k_mma_gemm(const float* __restrict__ A, const float* __restrict__ W,
           const float* __restrict__ bias, float* __restrict__ C, int M) {
    const int K = N_GENES;
    extern __shared__ float sm[];
    float* As[2] = { sm,               sm + 128 * TS };
    float* Bs[2] = { sm + 2 * 128 * TS, sm + 3 * 128 * TS };

    int tid  = threadIdx.x;
    int warp = tid >> 5;
    int lane = tid & 31;
    int wm = warp >> 2;           // 0..1
    int wn = warp & 3;            // 0..3
    int n0 = blockIdx.x * 128;
    int m0 = blockIdx.y * 128;
    int gq = lane >> 2;           // 0..7
    int gr = lane & 3;            // 0..3

    // per-thread load slots (4 float4 per matrix per stage)
    int lrow[4], lc4[4];
    bool lok[4];
    #pragma unroll
    for (int j = 0; j < 4; j++) {
        int slot = tid + 256 * j;          // 0..1023
        lrow[j] = slot >> 3;
        lc4[j]  = (slot & 7) * 4;
        lok[j]  = (m0 + lrow[j]) < M;
    }

    float acc[4][4][4];
    #pragma unroll
    for (int i = 0; i < 4; i++)
        #pragma unroll
        for (int j = 0; j < 4; j++)
            #pragma unroll
            for (int r = 0; r < 4; r++) acc[i][j][r] = 0.0f;

    // stage loader
    auto load_stage = [&](int kt, int buf) {
        #pragma unroll
        for (int j = 0; j < 4; j++) {
            cp16(smem_u32(&As[buf][lrow[j] * TS + lc4[j]]),
                 A + (size_t)(m0 + lrow[j]) * K + kt + lc4[j], lok[j]);
            cp16(smem_u32(&Bs[buf][lrow[j] * TS + lc4[j]]),
                 W + (size_t)(n0 + lrow[j]) * K + kt + lc4[j], true);
        }
        asm volatile("cp.async.commit_group;");
    };

    load_stage(0, 0);

    const int NIT = K / BK;       // 16
    for (int it = 0; it < NIT; it++) {
        asm volatile("cp.async.wait_group 0;");
        __syncthreads();
        if (it + 1 < NIT) load_stage((it + 1) * BK, (it + 1) & 1);

        float* Ab = As[it & 1];
        float* Bb = Bs[it & 1];
        #pragma unroll
        for (int s = 0; s < 4; s++) {
            int k0 = s * 8 + gr;
            int k1 = k0 + 4;
            float af[4][4], bf[4][2];
            #pragma unroll
            for (int mf = 0; mf < 4; mf++) {
                int r0 = wm * 64 + mf * 16 + gq;
                af[mf][0] = Ab[r0 * TS + k0];
                af[mf][1] = Ab[(r0 + 8) * TS + k0];
                af[mf][2] = Ab[r0 * TS + k1];
                af[mf][3] = Ab[(r0 + 8) * TS + k1];
            }
            #pragma unroll
            for (int nf = 0; nf < 4; nf++) {
                int cN = wn * 32 + nf * 8 + gq;
                bf[nf][0] = Bb[cN * TS + k0];
                bf[nf][1] = Bb[cN * TS + k1];
            }
            #pragma unroll
            for (int mf = 0; mf < 4; mf++)
                #pragma unroll
                for (int nf = 0; nf < 4; nf++)
                    mma_tf32(acc[mf][nf], af[mf], bf[nf]);
        }
        __syncthreads();
    }

    // epilogue
    #pragma unroll
    for (int mf = 0; mf < 4; mf++) {
        int r0 = m0 + wm * 64 + mf * 16 + gq;
        #pragma unroll
        for (int nf = 0; nf < 4; nf++) {
            int cN = n0 + wn * 32 + nf * 8 + gr * 2;
            float b0 = ADD_BIAS ? bias[cN]     : 0.0f;
            float b1 = ADD_BIAS ? bias[cN + 1] : 0.0f;
            if (r0 < M)
                *(float2*)(C + (size_t)r0 * N_GENES + cN) =
                    make_float2(acc[mf][nf][0] + b0, acc[mf][nf][1] + b1);
            if (r0 + 8 < M)
                *(float2*)(C + (size_t)(r0 + 8) * N_GENES + cN) =
                    make_float2(acc[mf][nf][2] + b0, acc[mf][nf][3] + b1);
        }
    }
}

// ---------------- CSR build: count, scan, bucket ----------------------------
__global__ void k_cnt(const int* __restrict__ dst) {
    int e = blockIdx.x * blockDim.x + threadIdx.x;
    if (e < N_EDGES) atomicAdd(&g_cnt[dst[e]], 1);
}

__global__ void k_scan1(void) {
    __shared__ int s[1024];
    int t = threadIdx.x;
    int i = blockIdx.x * 1024 + t;
    int v = (i < N_SPOTS) ? g_cnt[i] : 0;
    s[t] = v;
    __syncthreads();
    for (int off = 1; off < 1024; off <<= 1) {
        int a = (t >= off) ? s[t - off] : 0;
        __syncthreads();
        s[t] += a;
        __syncthreads();
    }
    if (i < N_SPOTS) g_off[i] = s[t] - v;
    if (t == 1023) g_bsum[blockIdx.x] = s[1023];
}

__global__ void k_scan2(void) {
    __shared__ int s[128];
    int t = threadIdx.x;
    int v = (t < SCAN_B) ? g_bsum[t] : 0;
    s[t] = v;
    __syncthreads();
    for (int off = 1; off < 128; off <<= 1) {
        int a = (t >= off) ? s[t - off] : 0;
        __syncthreads();
        s[t] += a;
        __syncthreads();
    }
    if (t < SCAN_B) g_bsum[t] = s[t] - v;
}

__global__ void k_scan3(void) {
    int i = blockIdx.x * blockDim.x + threadIdx.x;
    if (i < N_SPOTS) {
        int off = g_off[i] + g_bsum[i >> 10];
        g_off[i] = off;
        g_cur[i] = off;
        int c = g_cnt[i];
        g_dinv[i] = (c > 0) ? rsqrtf((float)c) : 0.0f;
    }
    if (i == 0) g_off[N_SPOTS] = N_EDGES;
}

__global__ void k_bucket(const int* __restrict__ src, const int* __restrict__ dst) {
    int e = blockIdx.x * blockDim.x + threadIdx.x;
    if (e < N_EDGES) {
        int pos = atomicAdd(&g_cur[dst[e]], 1);
        g_ebuf[pos] = src[e];
    }
}

// ---------------- gather: msg[d] = bc + sum_{src in bucket(d)} norm * x[src]
__global__ void k_gather(const float* __restrict__ bc, float* __restrict__ msg) {
    int d = blockIdx.x;
    int t = threadIdx.x;            // 0..127
    int beg = g_off[d], end = g_off[d + 1];
    float di = g_dinv[d];
    float4 acc = ((const float4*)bc)[t];
    for (int i = beg; i < end; i++) {
        int s = g_ebuf[i];
        float nrm = di * g_dinv[s];
        float4 v = ((const float4*)(g_x + (size_t)s * N_GENES))[t];
        acc.x = fmaf(nrm, v.x, acc.x);
        acc.y = fmaf(nrm, v.y, acc.y);
        acc.z = fmaf(nrm, v.z, acc.z);
        acc.w = fmaf(nrm, v.w, acc.w);
    }
    ((float4*)(msg + (size_t)d * N_GENES))[t] = acc;
}

// ---------------- column sums of gex ----------------------------------------
__global__ void k_colsum(void) {
    __shared__ float s[N_GENES];
    int t = threadIdx.x;
    s[t] = 0.0f; s[t + 256] = 0.0f;
    __syncthreads();
    for (int r = blockIdx.x; r < N_SPOTS; r += gridDim.x) {
        const float* row = g_gex + (size_t)r * N_GENES;
        s[t]       += row[t];
        s[t + 256] += row[t + 256];
    }
    __syncthreads();
    atomicAdd(&g_colsum[t], s[t]);
    atomicAdd(&g_colsum[t + 256], s[t + 256]);
}

// ---------------- mean-field scalar ----------------------------------------
__global__ void k_finalize(const float* __restrict__ Wc, const float* __restrict__ Wl,
                           float* __restrict__ out_scalar) {
    __shared__ float mean[N_GENES];
    __shared__ float red[N_GENES];
    int t = threadIdx.x;   // 512 threads
    mean[t] = g_colsum[t] * (1.0f / (float)N_SPOTS);
    __syncthreads();

    float v = 0.0f, u = 0.0f;
    const float* wc = Wc + (size_t)t * N_GENES;
    const float* wl = Wl + (size_t)t * N_GENES;
    for (int k = 0; k < N_GENES; k++) {
        float m = mean[k];
        v = fmaf((float)N_NEI * wc[k] + 2.0f * wl[k], m, v);
        u = fmaf(wl[k] + 0.5f * (float)N_NEI * wc[k], m, u);
    }

    red[t] = v * v;
    __syncthreads();
    for (int s = 256; s > 0; s >>= 1) {
        if (t < s) red[t] += red[t + s];
        __syncthreads();
    }
    float g2 = red[0];
    __syncthreads();

    red[t] = mean[t] * u;
    __syncthreads();
    for (int s = 256; s > 0; s >>= 1) {
        if (t < s) red[t] += red[t + s];
        __syncthreads();
    }
    if (t == 0) {
        float g = sqrtf(g2);
        float z_mean = -(float)N_SPOTS * red[0];
        float gc = fminf(g, 20.0f);
        float z_int;
        if (g > 20.0f)
            z_int = (float)N_SPOTS * (g - logf(g));
        else
            z_int = (float)N_SPOTS * logf((expf(gc) - expf(-gc)) / gc);
        out_scalar[0] = z_mean + z_int;
    }
}

// ---------------- launch ----------------------------------------------------
extern "C" void kernel_launch(void* const* d_in, const int* in_sizes, int n_in,
                              void* d_out, int out_size) {
    const float* sphex = (const float*)d_in[0];   // [100000, 511]
    const float* Wc    = (const float*)d_in[1];   // [512, 512]
    const float* bc    = (const float*)d_in[2];   // [512]
    const float* Wl    = (const float*)d_in[3];   // [512, 512]
    const float* bl    = (const float*)d_in[4];   // [512]
    const int*   eidx  = (const int*)d_in[5];     // [2, 600000]
    (void)in_sizes; (void)n_in; (void)out_size;

    const int* e_src = eidx;
    const int* e_dst = eidx + N_EDGES;

    float* out       = (float*)d_out;
    float* out_msg   = out;                                  // [N, G]
    float* out_intra = out + (size_t)N_SPOTS * N_GENES;      // [N, G]
    float* out_logz  = out + 2 * (size_t)N_SPOTS * N_GENES;  // [1]

    float *p_gex, *p_x, *p_wc, *p_wl;
    cudaGetSymbolAddress((void**)&p_gex, g_gex);
    cudaGetSymbolAddress((void**)&p_x,   g_x);
    cudaGetSymbolAddress((void**)&p_wc,  g_wc);
    cudaGetSymbolAddress((void**)&p_wl,  g_wl);

    // 0) zero counters + pre-round weights
    k_zero<<<(N_SPOTS + 255) / 256, 256>>>();
    k_cvtW<<<(N_GENES * N_GENES) / 256, 256>>>(Wc, Wl);

    // 1) CSR build (independent of gex/GEMM)
    k_cnt<<<(N_EDGES + 255) / 256, 256>>>(e_dst);
    k_scan1<<<SCAN_B, 1024>>>();
    k_scan2<<<1, 128>>>();
    k_scan3<<<(N_SPOTS + 255) / 256, 256>>>();
    k_bucket<<<(N_EDGES + 255) / 256, 256>>>(e_src, e_dst);

    // 2) gex (warp per row, tf32-rounded output)
    k_gex<<<(N_SPOTS * 32 + 255) / 256, 256>>>(sphex);

    // 3) split GEMMs (tf32 tensor cores, cp.async double buffered)
    {
        const int smem_bytes = 4 * 128 * TS * sizeof(float);  // 73728
        cudaFuncSetAttribute(k_mma_gemm<false>,
                             cudaFuncAttributeMaxDynamicSharedMemorySize, smem_bytes);
        cudaFuncSetAttribute(k_mma_gemm<true>,
                             cudaFuncAttributeMaxDynamicSharedMemorySize, smem_bytes);
        dim3 grid(N_GENES / 128, (N_SPOTS + 127) / 128);
        k_mma_gemm<false><<<grid, 256, smem_bytes>>>(p_gex, p_wc, nullptr, p_x, N_SPOTS);
        k_mma_gemm<true ><<<grid, 256, smem_bytes>>>(p_gex, p_wl, bl, out_intra, N_SPOTS);
    }

    // 4) gather per destination (bias folded in, no atomics)
    k_gather<<<N_SPOTS, 128>>>(bc, out_msg);

    // 5) column sums -> mean -> scalar
    k_colsum<<<512, 256>>>();
    k_finalize<<<1, 512>>>(Wc, Wl, out_logz);
}

// round 9
// speedup vs baseline: 1.6983x; 1.1502x over previous
#include <cuda_runtime.h>
#include <cuda_bf16.h>
#include <math.h>
#include <stdint.h>

// Problem constants (fixed by the dataset)
#define N_SPOTS   100000
#define N_GENES   512
#define N_SPH     511
#define N_EDGES   600000
#define N_NEI     6
#define SCAN_B    ((N_SPOTS + 1023) / 1024)   // 98
#define M_TILES   782                          // ceil(100000/128)
#define K_TILES   16                           // 512/32

// Permuted-layout sizes: tile = 128 rows x 32 k = 4096 floats
// A_perm: [m_tile][k_tile][chunk(16)][pos(256)]
__device__ float g_gexp[(size_t)M_TILES * K_TILES * 4096];  // 205 MB (tf32, padded)
__device__ float g_x  [(size_t)N_SPOTS * N_GENES];          // 204.8 MB
__device__ float g_wc [4 * K_TILES * 4096];                 // permuted tf32 Wc
__device__ float g_wl [4 * K_TILES * 4096];                 // permuted tf32 Wl
__device__ int   g_cnt[N_SPOTS];
__device__ int   g_off[N_SPOTS + 1];
__device__ int   g_cur[N_SPOTS];
__device__ int   g_ebuf[N_EDGES];
__device__ int   g_bsum[SCAN_B];
__device__ float g_dinv[N_SPOTS];
__device__ float g_colsum[N_GENES];

__device__ __forceinline__ float to_tf32(float x) {
    float r;
    asm("cvt.rna.tf32.f32 %0, %1;" : "=f"(r) : "f"(x));
    return r;
}

// ---------------- init ------------------------------------------------------
__global__ void k_zero(void) {
    int i = blockIdx.x * blockDim.x + threadIdx.x;
    if (i < N_SPOTS) g_cnt[i] = 0;
    if (i < N_GENES) g_colsum[i] = 0.0f;
}

// ---------------- weight pre-round to tf32, permuted B layout ----------------
// B quad per thread: [(cn,k0),(cn,k1),(cn+8,k0),(cn+8,k1)]
__global__ void k_cvtW(const float* __restrict__ Wc, const float* __restrict__ Wl) {
    int i = blockIdx.x * blockDim.x + threadIdx.x;   // 262144
    int n = i >> 9;          // W row = output col (0..511)
    int k = i & 511;
    int n0b = n >> 7, nl = n & 127;
    int kt  = k >> 5, kl = k & 31;
    int cb = nl >> 4, gq = nl & 7, e = (nl >> 3) & 1;
    int s  = kl >> 3, gr = kl & 3, h = (kl >> 2) & 1;
    size_t idx = ((size_t)(n0b * K_TILES + kt) * 16 + (s * 4 + gr)) * 256
               + (cb * 8 + gq) * 4 + (2 * e + h);
    g_wc[idx] = to_tf32(Wc[i]);
    g_wl[idx] = to_tf32(Wl[i]);
}

// ---------------- gex: block per 128-row tile, permuted output + colsum -----
// A quad per thread: [(q,k0),(q+8,k0),(q,k1),(q+8,k1)]
#define GEX_STRIDE 260     // staging chunk stride (floats)
__global__ void __launch_bounds__(256)
k_gex(const float* __restrict__ sphex) {
    __shared__ float sbuf[16 * GEX_STRIDE];  // one permuted 128x32 chunk
    __shared__ float scol[N_GENES];

    int tid  = threadIdx.x;
    int warp = tid >> 5;          // 0..7 -> 16-row block mb = warp
    int lane = tid & 31;
    int blk  = blockIdx.x;        // 0..781

    scol[tid] = 0.0f; scol[tid + 256] = 0.0f;
    __syncthreads();

    // per-lane copy of running sin-products for this warp's 16 rows
    float P[16];
    #pragma unroll
    for (int r = 0; r < 16; r++) P[r] = 1.0f;

    int s4 = lane >> 3, gr = lane & 3, h = (lane >> 2) & 1;
    int chunk = s4 * 4 + gr;

    for (int kc = 0; kc < K_TILES; kc++) {
        int col = kc * 32 + lane;
        float csum = 0.0f;
        #pragma unroll
        for (int rr = 0; rr < 16; rr++) {
            int row = blk * 128 + warp * 16 + rr;
            bool vrow = row < N_SPOTS;
            float sv = 1.0f, cv = 1.0f;
            if (vrow && col < N_SPH) {
                float xv = sphex[(size_t)row * N_SPH + col];
                sincosf(xv, &sv, &cv);
            }
            // inclusive warp product scan
            float incl = sv;
            #pragma unroll
            for (int off = 1; off < 32; off <<= 1) {
                float o = __shfl_up_sync(0xffffffffu, incl, off);
                if (lane >= off) incl *= o;
            }
            float excl = __shfl_up_sync(0xffffffffu, incl, 1);
            if (lane == 0) excl = 1.0f;
            float out = vrow ? to_tf32(P[rr] * excl * cv) : 0.0f;
            P[rr] *= __shfl_sync(0xffffffffu, incl, 31);
            csum += out;
            int q = rr & 7, p = rr >> 3;
            sbuf[chunk * GEX_STRIDE + (warp * 8 + q) * 4 + (p + 2 * h)] = out;
        }
        atomicAdd(&scol[kc * 32 + lane], csum);
        __syncthreads();
        // coalesced permuted store of this 128x32 tile
        float* dstt = g_gexp + (size_t)(blk * K_TILES + kc) * 4096;
        #pragma unroll
        for (int jj = 0; jj < 4; jj++) {
            int i = tid + 256 * jj;       // float4 slot 0..1023
            int gpos = i * 4;
            int ch = gpos >> 8, pos = gpos & 255;
            float4 v = *(const float4*)&sbuf[ch * GEX_STRIDE + pos];
            *(float4*)(dstt + gpos) = v;
        }
        __syncthreads();
    }
    atomicAdd(&g_colsum[tid],       scol[tid]);
    atomicAdd(&g_colsum[tid + 256], scol[tid + 256]);
}

// ---------------- TF32 tensor GEMM, permuted operands, cp.async 2-stage -----
#define CH_STRIDE 264      // smem chunk stride (floats): 16B-units ≡ 2 mod 8
#define STG_FLTS  (16 * CH_STRIDE)   // 4224 floats per matrix per stage

__device__ __forceinline__ uint32_t smem_u32(const void* p) {
    return (uint32_t)__cvta_generic_to_shared(p);
}
__device__ __forceinline__ void cp16(uint32_t dst, const void* src) {
    asm volatile("cp.async.ca.shared.global [%0], [%1], 16;"
                 :: "r"(dst), "l"(src));
}

__device__ __forceinline__ void mma_tf32(float* c, const float* a, const float* b) {
    const uint32_t* A = reinterpret_cast<const uint32_t*>(a);
    const uint32_t* B = reinterpret_cast<const uint32_t*>(b);
    asm volatile(
        "mma.sync.aligned.m16n8k8.row.col.f32.tf32.tf32.f32 "
        "{%0,%1,%2,%3}, {%4,%5,%6,%7}, {%8,%9}, {%0,%1,%2,%3};"
        : "+f"(c[0]), "+f"(c[1]), "+f"(c[2]), "+f"(c[3])
        : "r"(A[0]), "r"(A[1]), "r"(A[2]), "r"(A[3]), "r"(B[0]), "r"(B[1]));
}

template <bool ADD_BIAS>
__global__ void __launch_bounds__(256, 2)
k_mma_gemm(const float* __restrict__ Ap, const float* __restrict__ Bp,
           const float* __restrict__ bias, float* __restrict__ C, int M) {
    extern __shared__ float sm[];
    float* As[2] = { sm,                sm + STG_FLTS };
    float* Bs[2] = { sm + 2 * STG_FLTS, sm + 3 * STG_FLTS };

    int tid  = threadIdx.x;
    int warp = tid >> 5;
    int lane = tid & 31;
    int wm = warp >> 2;           // 0..1
    int wn = warp & 3;            // 0..3
    int n0b = blockIdx.x;         // 0..3
    int m0b = blockIdx.y;         // 0..781
    int gq = lane >> 2;           // 0..7
    int gr = lane & 3;            // 0..3

    const float* Atiles = Ap + (size_t)m0b * K_TILES * 4096;
    const float* Btiles = Bp + (size_t)n0b * K_TILES * 4096;

    float acc[4][4][4];
    #pragma unroll
    for (int i = 0; i < 4; i++)
        #pragma unroll
        for (int j = 0; j < 4; j++)
            #pragma unroll
            for (int r = 0; r < 4; r++) acc[i][j][r] = 0.0f;

    auto load_stage = [&](int kt, int buf) {
        #pragma unroll
        for (int j = 0; j < 4; j++) {
            int slot = tid + 256 * j;           // 0..1023 (16B chunks)
            int ch = slot >> 6, inner = slot & 63;
            int smoff = ch * CH_STRIDE + inner * 4;
            cp16(smem_u32(&As[buf][smoff]), Atiles + (size_t)kt * 4096 + slot * 4);
            cp16(smem_u32(&Bs[buf][smoff]), Btiles + (size_t)kt * 4096 + slot * 4);
        }
        asm volatile("cp.async.commit_group;");
    };

    load_stage(0, 0);

    for (int it = 0; it < K_TILES; it++) {
        asm volatile("cp.async.wait_group 0;");
        __syncthreads();
        if (it + 1 < K_TILES) load_stage(it + 1, (it + 1) & 1);

        const float* Ab = As[it & 1];
        const float* Bb = Bs[it & 1];
        #pragma unroll
        for (int s = 0; s < 4; s++) {
            int choff = (s * 4 + gr) * CH_STRIDE;
            float af[4][4], bf[4][2];
            #pragma unroll
            for (int mf = 0; mf < 4; mf++) {
                float4 aq = *(const float4*)&Ab[choff + ((wm * 4 + mf) * 8 + gq) * 4];
                af[mf][0] = aq.x; af[mf][1] = aq.y; af[mf][2] = aq.z; af[mf][3] = aq.w;
            }
            #pragma unroll
            for (int nfp = 0; nfp < 2; nfp++) {
                float4 bq = *(const float4*)&Bb[choff + ((wn * 2 + nfp) * 8 + gq) * 4];
                bf[2 * nfp][0]     = bq.x; bf[2 * nfp][1]     = bq.y;
                bf[2 * nfp + 1][0] = bq.z; bf[2 * nfp + 1][1] = bq.w;
            }
            #pragma unroll
            for (int mf = 0; mf < 4; mf++)
                #pragma unroll
                for (int nf = 0; nf < 4; nf++)
                    mma_tf32(acc[mf][nf], af[mf], bf[nf]);
        }
        __syncthreads();
    }

    // epilogue (C normal row-major layout)
    #pragma unroll
    for (int mf = 0; mf < 4; mf++) {
        int r0 = m0b * 128 + wm * 64 + mf * 16 + gq;
        #pragma unroll
        for (int nf = 0; nf < 4; nf++) {
            int cN = n0b * 128 + wn * 32 + nf * 8 + gr * 2;
            float b0 = ADD_BIAS ? bias[cN]     : 0.0f;
            float b1 = ADD_BIAS ? bias[cN + 1] : 0.0f;
            if (r0 < M)
                *(float2*)(C + (size_t)r0 * N_GENES + cN) =
                    make_float2(acc[mf][nf][0] + b0, acc[mf][nf][1] + b1);
            if (r0 + 8 < M)
                *(float2*)(C + (size_t)(r0 + 8) * N_GENES + cN) =
                    make_float2(acc[mf][nf][2] + b0, acc[mf][nf][3] + b1);
        }
    }
}

// ---------------- CSR build: count, scan, bucket ----------------------------
__global__ void k_cnt(const int* __restrict__ dst) {
    int e = blockIdx.x * blockDim.x + threadIdx.x;
    if (e < N_EDGES) atomicAdd(&g_cnt[dst[e]], 1);
}

__global__ void k_scan1(void) {
    __shared__ int s[1024];
    int t = threadIdx.x;
    int i = blockIdx.x * 1024 + t;
    int v = (i < N_SPOTS) ? g_cnt[i] : 0;
    s[t] = v;
    __syncthreads();
    for (int off = 1; off < 1024; off <<= 1) {
        int a = (t >= off) ? s[t - off] : 0;
        __syncthreads();
        s[t] += a;
        __syncthreads();
    }
    if (i < N_SPOTS) g_off[i] = s[t] - v;
    if (t == 1023) g_bsum[blockIdx.x] = s[1023];
}

__global__ void k_scan2(void) {
    __shared__ int s[128];
    int t = threadIdx.x;
    int v = (t < SCAN_B) ? g_bsum[t] : 0;
    s[t] = v;
    __syncthreads();
    for (int off = 1; off < 128; off <<= 1) {
        int a = (t >= off) ? s[t - off] : 0;
        __syncthreads();
        s[t] += a;
        __syncthreads();
    }
    if (t < SCAN_B) g_bsum[t] = s[t] - v;
}

__global__ void k_scan3(void) {
    int i = blockIdx.x * blockDim.x + threadIdx.x;
    if (i < N_SPOTS) {
        int off = g_off[i] + g_bsum[i >> 10];
        g_off[i] = off;
        g_cur[i] = off;
        int c = g_cnt[i];
        g_dinv[i] = (c > 0) ? rsqrtf((float)c) : 0.0f;
    }
    if (i == 0) g_off[N_SPOTS] = N_EDGES;
}

__global__ void k_bucket(const int* __restrict__ src, const int* __restrict__ dst) {
    int e = blockIdx.x * blockDim.x + threadIdx.x;
    if (e < N_EDGES) {
        int pos = atomicAdd(&g_cur[dst[e]], 1);
        g_ebuf[pos] = src[e];
    }
}

// ---------------- gather: msg[d] = bc + sum_{src in bucket(d)} norm * x[src]
__global__ void k_gather(const float* __restrict__ bc, float* __restrict__ msg) {
    int d = blockIdx.x;
    int t = threadIdx.x;            // 0..127
    int beg = g_off[d], end = g_off[d + 1];
    float di = g_dinv[d];
    float4 acc = ((const float4*)bc)[t];
    for (int i = beg; i < end; i++) {
        int s = g_ebuf[i];
        float nrm = di * g_dinv[s];
        float4 v = ((const float4*)(g_x + (size_t)s * N_GENES))[t];
        acc.x = fmaf(nrm, v.x, acc.x);
        acc.y = fmaf(nrm, v.y, acc.y);
        acc.z = fmaf(nrm, v.z, acc.z);
        acc.w = fmaf(nrm, v.w, acc.w);
    }
    ((float4*)(msg + (size_t)d * N_GENES))[t] = acc;
}

// ---------------- mean-field scalar ----------------------------------------
__global__ void k_finalize(const float* __restrict__ Wc, const float* __restrict__ Wl,
                           float* __restrict__ out_scalar) {
    __shared__ float mean[N_GENES];
    __shared__ float red[N_GENES];
    int t = threadIdx.x;   // 512 threads
    mean[t] = g_colsum[t] * (1.0f / (float)N_SPOTS);
    __syncthreads();

    float v = 0.0f, u = 0.0f;
    const float* wc = Wc + (size_t)t * N_GENES;
    const float* wl = Wl + (size_t)t * N_GENES;
    for (int k = 0; k < N_GENES; k++) {
        float m = mean[k];
        v = fmaf((float)N_NEI * wc[k] + 2.0f * wl[k], m, v);
        u = fmaf(wl[k] + 0.5f * (float)N_NEI * wc[k], m, u);
    }

    red[t] = v * v;
    __syncthreads();
    for (int s = 256; s > 0; s >>= 1) {
        if (t < s) red[t] += red[t + s];
        __syncthreads();
    }
    float g2 = red[0];
    __syncthreads();

    red[t] = mean[t] * u;
    __syncthreads();
    for (int s = 256; s > 0; s >>= 1) {
        if (t < s) red[t] += red[t + s];
        __syncthreads();
    }
    if (t == 0) {
        float g = sqrtf(g2);
        float z_mean = -(float)N_SPOTS * red[0];
        float gc = fminf(g, 20.0f);
        float z_int;
        if (g > 20.0f)
            z_int = (float)N_SPOTS * (g - logf(g));
        else
            z_int = (float)N_SPOTS * logf((expf(gc) - expf(-gc)) / gc);
        out_scalar[0] = z_mean + z_int;
    }
}

// ---------------- launch ----------------------------------------------------
extern "C" void kernel_launch(void* const* d_in, const int* in_sizes, int n_in,
                              void* d_out, int out_size) {
    const float* sphex = (const float*)d_in[0];   // [100000, 511]
    const float* Wc    = (const float*)d_in[1];   // [512, 512]
    const float* bc    = (const float*)d_in[2];   // [512]
    const float* Wl    = (const float*)d_in[3];   // [512, 512]
    const float* bl    = (const float*)d_in[4];   // [512]
    const int*   eidx  = (const int*)d_in[5];     // [2, 600000]
    (void)in_sizes; (void)n_in; (void)out_size;

    const int* e_src = eidx;
    const int* e_dst = eidx + N_EDGES;

    float* out       = (float*)d_out;
    float* out_msg   = out;                                  // [N, G]
    float* out_intra = out + (size_t)N_SPOTS * N_GENES;      // [N, G]
    float* out_logz  = out + 2 * (size_t)N_SPOTS * N_GENES;  // [1]

    float *p_gexp, *p_x, *p_wc, *p_wl;
    cudaGetSymbolAddress((void**)&p_gexp, g_gexp);
    cudaGetSymbolAddress((void**)&p_x,    g_x);
    cudaGetSymbolAddress((void**)&p_wc,   g_wc);
    cudaGetSymbolAddress((void**)&p_wl,   g_wl);

    // 0) zero counters + pre-round/permute weights
    k_zero<<<(N_SPOTS + 255) / 256, 256>>>();
    k_cvtW<<<(N_GENES * N_GENES) / 256, 256>>>(Wc, Wl);

    // 1) CSR build (independent of gex/GEMM)
    k_cnt<<<(N_EDGES + 255) / 256, 256>>>(e_dst);
    k_scan1<<<SCAN_B, 1024>>>();
    k_scan2<<<1, 128>>>();
    k_scan3<<<(N_SPOTS + 255) / 256, 256>>>();
    k_bucket<<<(N_EDGES + 255) / 256, 256>>>(e_src, e_dst);

    // 2) gex (block per 128-row tile, permuted output + fused colsum)
    k_gex<<<M_TILES, 256>>>(sphex);

    // 3) split GEMMs (tf32 tensor cores, permuted operands, cp.async)
    {
        const int smem_bytes = 4 * STG_FLTS * sizeof(float);  // 67584
        cudaFuncSetAttribute(k_mma_gemm<false>,
                             cudaFuncAttributeMaxDynamicSharedMemorySize, smem_bytes);
        cudaFuncSetAttribute(k_mma_gemm<true>,
                             cudaFuncAttributeMaxDynamicSharedMemorySize, smem_bytes);
        dim3 grid(4, M_TILES);
        k_mma_gemm<false><<<grid, 256, smem_bytes>>>(p_gexp, p_wc, nullptr, p_x, N_SPOTS);
        k_mma_gemm<true ><<<grid, 256, smem_bytes>>>(p_gexp, p_wl, bl, out_intra, N_SPOTS);
    }

    // 4) gather per destination (bias folded in, no atomics)
    k_gather<<<N_SPOTS, 128>>>(bc, out_msg);

    // 5) mean-field scalar (colsum already accumulated by k_gex)
    k_finalize<<<1, 512>>>(Wc, Wl, out_logz);
}

// round 14
// speedup vs baseline: 1.6997x; 1.0008x over previous
#include <cuda_runtime.h>
#include <cuda_bf16.h>
#include <math.h>
#include <stdint.h>

// Problem constants (fixed by the dataset)
#define N_SPOTS   100000
#define N_GENES   512
#define N_SPH     511
#define N_EDGES   600000
#define N_NEI     6
#define SCAN_B    ((N_SPOTS + 1023) / 1024)   // 98
#define M_TILES   782                          // ceil(100000/128)
#define K_TILES   16                           // 512/32

// Permuted-layout sizes: tile = 128 rows x 32 k = 4096 floats
// A_perm: [m_tile][k_tile][chunk(16)][pos(256)]
__device__ float g_gexp[(size_t)M_TILES * K_TILES * 4096];  // 205 MB (tf32, padded)
__device__ float g_x  [(size_t)N_SPOTS * N_GENES];          // 204.8 MB
__device__ float g_wc [4 * K_TILES * 4096];                 // permuted tf32 Wc
__device__ float g_wl [4 * K_TILES * 4096];                 // permuted tf32 Wl
__device__ int   g_cnt[N_SPOTS];
__device__ int   g_off[N_SPOTS + 1];
__device__ int   g_cur[N_SPOTS];
__device__ int   g_ebuf[N_EDGES];
__device__ int   g_bsum[SCAN_B];
__device__ float g_dinv[N_SPOTS];
__device__ float g_colsum[N_GENES];

__device__ __forceinline__ float to_tf32(float x) {
    float r;
    asm("cvt.rna.tf32.f32 %0, %1;" : "=f"(r) : "f"(x));
    return r;
}

// ---------------- init ------------------------------------------------------
__global__ void k_zero(void) {
    int i = blockIdx.x * blockDim.x + threadIdx.x;
    if (i < N_SPOTS) g_cnt[i] = 0;
    if (i < N_GENES) g_colsum[i] = 0.0f;
}

// ---------------- weight pre-round to tf32, permuted B layout ----------------
// B quad per thread: [(cn,k0),(cn,k1),(cn+8,k0),(cn+8,k1)]
__global__ void k_cvtW(const float* __restrict__ Wc, const float* __restrict__ Wl) {
    int i = blockIdx.x * blockDim.x + threadIdx.x;   // 262144
    int n = i >> 9;          // W row = output col (0..511)
    int k = i & 511;
    int n0b = n >> 7, nl = n & 127;
    int kt  = k >> 5, kl = k & 31;
    int cb = nl >> 4, gq = nl & 7, e = (nl >> 3) & 1;
    int s  = kl >> 3, gr = kl & 3, h = (kl >> 2) & 1;
    size_t idx = ((size_t)(n0b * K_TILES + kt) * 16 + (s * 4 + gr)) * 256
               + (cb * 8 + gq) * 4 + (2 * e + h);
    g_wc[idx] = to_tf32(Wc[i]);
    g_wl[idx] = to_tf32(Wl[i]);
}

// ---------------- gex: block per 128-row tile, permuted output + colsum -----
// A quad per thread: [(q,k0),(q+8,k0),(q,k1),(q+8,k1)]
#define GEX_STRIDE 260     // staging chunk stride (floats)
__global__ void __launch_bounds__(256)
k_gex(const float* __restrict__ sphex) {
    __shared__ float sbuf[16 * GEX_STRIDE];  // one permuted 128x32 chunk
    __shared__ float scol[N_GENES];

    int tid  = threadIdx.x;
    int warp = tid >> 5;          // 0..7 -> 16-row block mb = warp
    int lane = tid & 31;
    int blk  = blockIdx.x;        // 0..781

    scol[tid] = 0.0f; scol[tid + 256] = 0.0f;
    __syncthreads();

    // per-lane copy of running sin-products for this warp's 16 rows
    float P[16];
    #pragma unroll
    for (int r = 0; r < 16; r++) P[r] = 1.0f;

    int s4 = lane >> 3, gr = lane & 3, h = (lane >> 2) & 1;
    int chunk = s4 * 4 + gr;

    for (int kc = 0; kc < K_TILES; kc++) {
        int col = kc * 32 + lane;
        float csum = 0.0f;
        #pragma unroll
        for (int rr = 0; rr < 16; rr++) {
            int row = blk * 128 + warp * 16 + rr;
            bool vrow = row < N_SPOTS;
            float sv = 1.0f, cv = 1.0f;
            if (vrow && col < N_SPH) {
                float xv = sphex[(size_t)row * N_SPH + col];
                sincosf(xv, &sv, &cv);
            }
            // inclusive warp product scan
            float incl = sv;
            #pragma unroll
            for (int off = 1; off < 32; off <<= 1) {
                float o = __shfl_up_sync(0xffffffffu, incl, off);
                if (lane >= off) incl *= o;
            }
            float excl = __shfl_up_sync(0xffffffffu, incl, 1);
            if (lane == 0) excl = 1.0f;
            float out = vrow ? to_tf32(P[rr] * excl * cv) : 0.0f;
            P[rr] *= __shfl_sync(0xffffffffu, incl, 31);
            csum += out;
            int q = rr & 7, p = rr >> 3;
            sbuf[chunk * GEX_STRIDE + (warp * 8 + q) * 4 + (p + 2 * h)] = out;
        }
        atomicAdd(&scol[kc * 32 + lane], csum);
        __syncthreads();
        // coalesced permuted store of this 128x32 tile
        float* dstt = g_gexp + (size_t)(blk * K_TILES + kc) * 4096;
        #pragma unroll
        for (int jj = 0; jj < 4; jj++) {
            int i = tid + 256 * jj;       // float4 slot 0..1023
            int gpos = i * 4;
            int ch = gpos >> 8, pos = gpos & 255;
            float4 v = *(const float4*)&sbuf[ch * GEX_STRIDE + pos];
            *(float4*)(dstt + gpos) = v;
        }
        __syncthreads();
    }
    atomicAdd(&g_colsum[tid],       scol[tid]);
    atomicAdd(&g_colsum[tid + 256], scol[tid + 256]);
}

// ---------------- TF32 tensor GEMM, permuted operands, cp.async 2-stage -----
#define CH_STRIDE 264      // smem chunk stride (floats): 16B-units ≡ 2 mod 8
#define STG_FLTS  (16 * CH_STRIDE)   // 4224 floats per matrix per stage

__device__ __forceinline__ uint32_t smem_u32(const void* p) {
    return (uint32_t)__cvta_generic_to_shared(p);
}
__device__ __forceinline__ void cp16(uint32_t dst, const void* src) {
    asm volatile("cp.async.ca.shared.global [%0], [%1], 16;"
                 :: "r"(dst), "l"(src));
}

__device__ __forceinline__ void mma_tf32(float* c, const float* a, const float* b) {
    const uint32_t* A = reinterpret_cast<const uint32_t*>(a);
    const uint32_t* B = reinterpret_cast<const uint32_t*>(b);
    asm volatile(
        "mma.sync.aligned.m16n8k8.row.col.f32.tf32.tf32.f32 "
        "{%0,%1,%2,%3}, {%4,%5,%6,%7}, {%8,%9}, {%0,%1,%2,%3};"
        : "+f"(c[0]), "+f"(c[1]), "+f"(c[2]), "+f"(c[3])
        : "r"(A[0]), "r"(A[1]), "r"(A[2]), "r"(A[3]), "r"(B[0]), "r"(B[1]));
}

template <bool ADD_BIAS>
__global__ void __launch_bounds__(256, 2)
k_mma_gemm(const float* __restrict__ Ap, const float* __restrict__ Bp,
           const float* __restrict__ bias, float* __restrict__ C, int M) {
    extern __shared__ float sm[];
    float* As[2] = { sm,                sm + STG_FLTS };
    float* Bs[2] = { sm + 2 * STG_FLTS, sm + 3 * STG_FLTS };

    int tid  = threadIdx.x;
    int warp = tid >> 5;
    int lane = tid & 31;
    int wm = warp >> 2;           // 0..1
    int wn = warp & 3;            // 0..3
    int n0b = blockIdx.x;         // 0..3
    int m0b = blockIdx.y;         // 0..781
    int gq = lane >> 2;           // 0..7
    int gr = lane & 3;            // 0..3

    const float* Atiles = Ap + (size_t)m0b * K_TILES * 4096;
    const float* Btiles = Bp + (size_t)n0b * K_TILES * 4096;

    float acc[4][4][4];
    #pragma unroll
    for (int i = 0; i < 4; i++)
        #pragma unroll
        for (int j = 0; j < 4; j++)
            #pragma unroll
            for (int r = 0; r < 4; r++) acc[i][j][r] = 0.0f;

    auto load_stage = [&](int kt, int buf) {
        #pragma unroll
        for (int j = 0; j < 4; j++) {
            int slot = tid + 256 * j;           // 0..1023 (16B chunks)
            int ch = slot >> 6, inner = slot & 63;
            int smoff = ch * CH_STRIDE + inner * 4;
            cp16(smem_u32(&As[buf][smoff]), Atiles + (size_t)kt * 4096 + slot * 4);
            cp16(smem_u32(&Bs[buf][smoff]), Btiles + (size_t)kt * 4096 + slot * 4);
        }
        asm volatile("cp.async.commit_group;");
    };

    load_stage(0, 0);

    for (int it = 0; it < K_TILES; it++) {
        asm volatile("cp.async.wait_group 0;");
        __syncthreads();
        if (it + 1 < K_TILES) load_stage(it + 1, (it + 1) & 1);

        const float* Ab = As[it & 1];
        const float* Bb = Bs[it & 1];
        #pragma unroll
        for (int s = 0; s < 4; s++) {
            int choff = (s * 4 + gr) * CH_STRIDE;
            float af[4][4], bf[4][2];
            #pragma unroll
            for (int mf = 0; mf < 4; mf++) {
                float4 aq = *(const float4*)&Ab[choff + ((wm * 4 + mf) * 8 + gq) * 4];
                af[mf][0] = aq.x; af[mf][1] = aq.y; af[mf][2] = aq.z; af[mf][3] = aq.w;
            }
            #pragma unroll
            for (int nfp = 0; nfp < 2; nfp++) {
                float4 bq = *(const float4*)&Bb[choff + ((wn * 2 + nfp) * 8 + gq) * 4];
                bf[2 * nfp][0]     = bq.x; bf[2 * nfp][1]     = bq.y;
                bf[2 * nfp + 1][0] = bq.z; bf[2 * nfp + 1][1] = bq.w;
            }
            #pragma unroll
            for (int mf = 0; mf < 4; mf++)
                #pragma unroll
                for (int nf = 0; nf < 4; nf++)
                    mma_tf32(acc[mf][nf], af[mf], bf[nf]);
        }
        __syncthreads();
    }

    // epilogue (C normal row-major layout)
    #pragma unroll
    for (int mf = 0; mf < 4; mf++) {
        int r0 = m0b * 128 + wm * 64 + mf * 16 + gq;
        #pragma unroll
        for (int nf = 0; nf < 4; nf++) {
            int cN = n0b * 128 + wn * 32 + nf * 8 + gr * 2;
            float b0 = ADD_BIAS ? bias[cN]     : 0.0f;
            float b1 = ADD_BIAS ? bias[cN + 1] : 0.0f;
            if (r0 < M)
                *(float2*)(C + (size_t)r0 * N_GENES + cN) =
                    make_float2(acc[mf][nf][0] + b0, acc[mf][nf][1] + b1);
            if (r0 + 8 < M)
                *(float2*)(C + (size_t)(r0 + 8) * N_GENES + cN) =
                    make_float2(acc[mf][nf][2] + b0, acc[mf][nf][3] + b1);
        }
    }
}

// ---------------- CSR build: count, scan, bucket ----------------------------
__global__ void k_cnt(const int* __restrict__ dst) {
    int e = blockIdx.x * blockDim.x + threadIdx.x;
    if (e < N_EDGES) atomicAdd(&g_cnt[dst[e]], 1);
}

__global__ void k_scan1(void) {
    __shared__ int s[1024];
    int t = threadIdx.x;
    int i = blockIdx.x * 1024 + t;
    int v = (i < N_SPOTS) ? g_cnt[i] : 0;
    s[t] = v;
    __syncthreads();
    for (int off = 1; off < 1024; off <<= 1) {
        int a = (t >= off) ? s[t - off] : 0;
        __syncthreads();
        s[t] += a;
        __syncthreads();
    }
    if (i < N_SPOTS) g_off[i] = s[t] - v;
    if (t == 1023) g_bsum[blockIdx.x] = s[1023];
}

__global__ void k_scan2(void) {
    __shared__ int s[128];
    int t = threadIdx.x;
    int v = (t < SCAN_B) ? g_bsum[t] : 0;
    s[t] = v;
    __syncthreads();
    for (int off = 1; off < 128; off <<= 1) {
        int a = (t >= off) ? s[t - off] : 0;
        __syncthreads();
        s[t] += a;
        __syncthreads();
    }
    if (t < SCAN_B) g_bsum[t] = s[t] - v;
}

__global__ void k_scan3(void) {
    int i = blockIdx.x * blockDim.x + threadIdx.x;
    if (i < N_SPOTS) {
        int off = g_off[i] + g_bsum[i >> 10];
        g_off[i] = off;
        g_cur[i] = off;
        int c = g_cnt[i];
        g_dinv[i] = (c > 0) ? rsqrtf((float)c) : 0.0f;
    }
    if (i == 0) g_off[N_SPOTS] = N_EDGES;
}

__global__ void k_bucket(const int* __restrict__ src, const int* __restrict__ dst) {
    int e = blockIdx.x * blockDim.x + threadIdx.x;
    if (e < N_EDGES) {
        int pos = atomicAdd(&g_cur[dst[e]], 1);
        g_ebuf[pos] = src[e];
    }
}

// ---------------- gather: msg[d] = bc + sum_{src in bucket(d)} norm * x[src]
__global__ void k_gather(const float* __restrict__ bc, float* __restrict__ msg) {
    int d = blockIdx.x;
    int t = threadIdx.x;            // 0..127
    int beg = g_off[d], end = g_off[d + 1];
    float di = g_dinv[d];
    float4 acc = ((const float4*)bc)[t];
    for (int i = beg; i < end; i++) {
        int s = g_ebuf[i];
        float nrm = di * g_dinv[s];
        float4 v = ((const float4*)(g_x + (size_t)s * N_GENES))[t];
        acc.x = fmaf(nrm, v.x, acc.x);
        acc.y = fmaf(nrm, v.y, acc.y);
        acc.z = fmaf(nrm, v.z, acc.z);
        acc.w = fmaf(nrm, v.w, acc.w);
    }
    ((float4*)(msg + (size_t)d * N_GENES))[t] = acc;
}

// ---------------- mean-field scalar ----------------------------------------
__global__ void k_finalize(const float* __restrict__ Wc, const float* __restrict__ Wl,
                           float* __restrict__ out_scalar) {
    __shared__ float mean[N_GENES];
    __shared__ float red[N_GENES];
    int t = threadIdx.x;   // 512 threads
    mean[t] = g_colsum[t] * (1.0f / (float)N_SPOTS);
    __syncthreads();

    float v = 0.0f, u = 0.0f;
    const float* wc = Wc + (size_t)t * N_GENES;
    const float* wl = Wl + (size_t)t * N_GENES;
    for (int k = 0; k < N_GENES; k++) {
        float m = mean[k];
        v = fmaf((float)N_NEI * wc[k] + 2.0f * wl[k], m, v);
        u = fmaf(wl[k] + 0.5f * (float)N_NEI * wc[k], m, u);
    }

    red[t] = v * v;
    __syncthreads();
    for (int s = 256; s > 0; s >>= 1) {
        if (t < s) red[t] += red[t + s];
        __syncthreads();
    }
    float g2 = red[0];
    __syncthreads();

    red[t] = mean[t] * u;
    __syncthreads();
    for (int s = 256; s > 0; s >>= 1) {
        if (t < s) red[t] += red[t + s];
        __syncthreads();
    }
    if (t == 0) {
        float g = sqrtf(g2);
        float z_mean = -(float)N_SPOTS * red[0];
        float gc = fminf(g, 20.0f);
        float z_int;
        if (g > 20.0f)
            z_int = (float)N_SPOTS * (g - logf(g));
        else
            z_int = (float)N_SPOTS * logf((expf(gc) - expf(-gc)) / gc);
        out_scalar[0] = z_mean + z_int;
    }
}

// ---------------- launch ----------------------------------------------------
extern "C" void kernel_launch(void* const* d_in, const int* in_sizes, int n_in,
                              void* d_out, int out_size) {
    const float* sphex = (const float*)d_in[0];   // [100000, 511]
    const float* Wc    = (const float*)d_in[1];   // [512, 512]
    const float* bc    = (const float*)d_in[2];   // [512]
    const float* Wl    = (const float*)d_in[3];   // [512, 512]
    const float* bl    = (const float*)d_in[4];   // [512]
    const int*   eidx  = (const int*)d_in[5];     // [2, 600000]
    (void)in_sizes; (void)n_in; (void)out_size;

    const int* e_src = eidx;
    const int* e_dst = eidx + N_EDGES;

    float* out       = (float*)d_out;
    float* out_msg   = out;                                  // [N, G]
    float* out_intra = out + (size_t)N_SPOTS * N_GENES;      // [N, G]
    float* out_logz  = out + 2 * (size_t)N_SPOTS * N_GENES;  // [1]

    float *p_gexp, *p_x, *p_wc, *p_wl;
    cudaGetSymbolAddress((void**)&p_gexp, g_gexp);
    cudaGetSymbolAddress((void**)&p_x,    g_x);
    cudaGetSymbolAddress((void**)&p_wc,   g_wc);
    cudaGetSymbolAddress((void**)&p_wl,   g_wl);

    // 0) zero counters + pre-round/permute weights
    k_zero<<<(N_SPOTS + 255) / 256, 256>>>();
    k_cvtW<<<(N_GENES * N_GENES) / 256, 256>>>(Wc, Wl);

    // 1) CSR build (independent of gex/GEMM)
    k_cnt<<<(N_EDGES + 255) / 256, 256>>>(e_dst);
    k_scan1<<<SCAN_B, 1024>>>();
    k_scan2<<<1, 128>>>();
    k_scan3<<<(N_SPOTS + 255) / 256, 256>>>();
    k_bucket<<<(N_EDGES + 255) / 256, 256>>>(e_src, e_dst);

    // 2) gex (block per 128-row tile, permuted output + fused colsum)
    k_gex<<<M_TILES, 256>>>(sphex);

    // 3) split GEMMs (tf32 tensor cores, permuted operands, cp.async)
    {
        const int smem_bytes = 4 * STG_FLTS * sizeof(float);  // 67584
        cudaFuncSetAttribute(k_mma_gemm<false>,
                             cudaFuncAttributeMaxDynamicSharedMemorySize, smem_bytes);
        cudaFuncSetAttribute(k_mma_gemm<true>,
                             cudaFuncAttributeMaxDynamicSharedMemorySize, smem_bytes);
        dim3 grid(4, M_TILES);
        k_mma_gemm<false><<<grid, 256, smem_bytes>>>(p_gexp, p_wc, nullptr, p_x, N_SPOTS);
        k_mma_gemm<true ><<<grid, 256, smem_bytes>>>(p_gexp, p_wl, bl, out_intra, N_SPOTS);
    }

    // 4) gather per destination (bias folded in, no atomics)
    k_gather<<<N_SPOTS, 128>>>(bc, out_msg);

    // 5) mean-field scalar (colsum already accumulated by k_gex)
    k_finalize<<<1, 512>>>(Wc, Wl, out_logz);
}

// round 15
// speedup vs baseline: 1.6998x; 1.0001x over previous
#include <cuda_runtime.h>
#include <cuda_bf16.h>
#include <math.h>
#include <stdint.h>

// Problem constants (fixed by the dataset)
#define N_SPOTS   100000
#define N_GENES   512
#define N_SPH     511
#define N_EDGES   600000
#define N_NEI     6
#define SCAN_B    ((N_SPOTS + 1023) / 1024)   // 98
#define M_TILES   782                          // ceil(100000/128)
#define K_TILES   16                           // 512/32

// Permuted-layout sizes: tile = 128 rows x 32 k = 4096 floats
// A_perm: [m_tile][k_tile][chunk(16)][pos(256)]
__device__ float g_gexp[(size_t)M_TILES * K_TILES * 4096];  // 205 MB (tf32, padded)
__device__ float g_x  [(size_t)N_SPOTS * N_GENES];          // 204.8 MB
__device__ float g_wc [4 * K_TILES * 4096];                 // permuted tf32 Wc
__device__ float g_wl [4 * K_TILES * 4096];                 // permuted tf32 Wl
__device__ int   g_cnt[N_SPOTS];
__device__ int   g_off[N_SPOTS + 1];
__device__ int   g_cur[N_SPOTS];
__device__ int   g_ebuf[N_EDGES];
__device__ int   g_bsum[SCAN_B];
__device__ float g_dinv[N_SPOTS];
__device__ float g_colsum[N_GENES];

__device__ __forceinline__ float to_tf32(float x) {
    float r;
    asm("cvt.rna.tf32.f32 %0, %1;" : "=f"(r) : "f"(x));
    return r;
}

// ---------------- init ------------------------------------------------------
__global__ void k_zero(void) {
    int i = blockIdx.x * blockDim.x + threadIdx.x;
    if (i < N_SPOTS) g_cnt[i] = 0;
    if (i < N_GENES) g_colsum[i] = 0.0f;
}

// ---------------- weight pre-round to tf32, permuted B layout ----------------
// B quad per thread: [(cn,k0),(cn,k1),(cn+8,k0),(cn+8,k1)]
__global__ void k_cvtW(const float* __restrict__ Wc, const float* __restrict__ Wl) {
    int i = blockIdx.x * blockDim.x + threadIdx.x;   // 262144
    int n = i >> 9;          // W row = output col (0..511)
    int k = i & 511;
    int n0b = n >> 7, nl = n & 127;
    int kt  = k >> 5, kl = k & 31;
    int cb = nl >> 4, gq = nl & 7, e = (nl >> 3) & 1;
    int s  = kl >> 3, gr = kl & 3, h = (kl >> 2) & 1;
    size_t idx = ((size_t)(n0b * K_TILES + kt) * 16 + (s * 4 + gr)) * 256
               + (cb * 8 + gq) * 4 + (2 * e + h);
    g_wc[idx] = to_tf32(Wc[i]);
    g_wl[idx] = to_tf32(Wl[i]);
}

// ---------------- gex: block per 128-row tile, permuted output + colsum -----
// A quad per thread: [(q,k0),(q+8,k0),(q,k1),(q+8,k1)]
#define GEX_STRIDE 260     // staging chunk stride (floats)
__global__ void __launch_bounds__(256)
k_gex(const float* __restrict__ sphex) {
    __shared__ float sbuf[16 * GEX_STRIDE];  // one permuted 128x32 chunk
    __shared__ float scol[N_GENES];

    int tid  = threadIdx.x;
    int warp = tid >> 5;          // 0..7 -> 16-row block mb = warp
    int lane = tid & 31;
    int blk  = blockIdx.x;        // 0..781

    scol[tid] = 0.0f; scol[tid + 256] = 0.0f;
    __syncthreads();

    // per-lane copy of running sin-products for this warp's 16 rows
    float P[16];
    #pragma unroll
    for (int r = 0; r < 16; r++) P[r] = 1.0f;

    int s4 = lane >> 3, gr = lane & 3, h = (lane >> 2) & 1;
    int chunk = s4 * 4 + gr;

    for (int kc = 0; kc < K_TILES; kc++) {
        int col = kc * 32 + lane;
        float csum = 0.0f;
        #pragma unroll
        for (int rr = 0; rr < 16; rr++) {
            int row = blk * 128 + warp * 16 + rr;
            bool vrow = row < N_SPOTS;
            float sv = 1.0f, cv = 1.0f;
            if (vrow && col < N_SPH) {
                float xv = sphex[(size_t)row * N_SPH + col];
                sincosf(xv, &sv, &cv);
            }
            // inclusive warp product scan
            float incl = sv;
            #pragma unroll
            for (int off = 1; off < 32; off <<= 1) {
                float o = __shfl_up_sync(0xffffffffu, incl, off);
                if (lane >= off) incl *= o;
            }
            float excl = __shfl_up_sync(0xffffffffu, incl, 1);
            if (lane == 0) excl = 1.0f;
            float out = vrow ? to_tf32(P[rr] * excl * cv) : 0.0f;
            P[rr] *= __shfl_sync(0xffffffffu, incl, 31);
            csum += out;
            int q = rr & 7, p = rr >> 3;
            sbuf[chunk * GEX_STRIDE + (warp * 8 + q) * 4 + (p + 2 * h)] = out;
        }
        atomicAdd(&scol[kc * 32 + lane], csum);
        __syncthreads();
        // coalesced permuted store of this 128x32 tile
        float* dstt = g_gexp + (size_t)(blk * K_TILES + kc) * 4096;
        #pragma unroll
        for (int jj = 0; jj < 4; jj++) {
            int i = tid + 256 * jj;       // float4 slot 0..1023
            int gpos = i * 4;
            int ch = gpos >> 8, pos = gpos & 255;
            float4 v = *(const float4*)&sbuf[ch * GEX_STRIDE + pos];
            *(float4*)(dstt + gpos) = v;
        }
        __syncthreads();
    }
    atomicAdd(&g_colsum[tid],       scol[tid]);
    atomicAdd(&g_colsum[tid + 256], scol[tid + 256]);
}

// ---------------- TF32 tensor GEMM, permuted operands, cp.async 2-stage -----
#define CH_STRIDE 264      // smem chunk stride (floats): 16B-units ≡ 2 mod 8
#define STG_FLTS  (16 * CH_STRIDE)   // 4224 floats per matrix per stage

__device__ __forceinline__ uint32_t smem_u32(const void* p) {
    return (uint32_t)__cvta_generic_to_shared(p);
}
__device__ __forceinline__ void cp16(uint32_t dst, const void* src) {
    asm volatile("cp.async.ca.shared.global [%0], [%1], 16;"
                 :: "r"(dst), "l"(src));
}

__device__ __forceinline__ void mma_tf32(float* c, const float* a, const float* b) {
    const uint32_t* A = reinterpret_cast<const uint32_t*>(a);
    const uint32_t* B = reinterpret_cast<const uint32_t*>(b);
    asm volatile(
        "mma.sync.aligned.m16n8k8.row.col.f32.tf32.tf32.f32 "
        "{%0,%1,%2,%3}, {%4,%5,%6,%7}, {%8,%9}, {%0,%1,%2,%3};"
        : "+f"(c[0]), "+f"(c[1]), "+f"(c[2]), "+f"(c[3])
        : "r"(A[0]), "r"(A[1]), "r"(A[2]), "r"(A[3]), "r"(B[0]), "r"(B[1]));
}

template <bool ADD_BIAS>
__global__ void __launch_bounds__(256, 2)
k_mma_gemm(const float* __restrict__ Ap, const float* __restrict__ Bp,
           const float* __restrict__ bias, float* __restrict__ C, int M) {
    extern __shared__ float sm[];
    float* As[2] = { sm,                sm + STG_FLTS };
    float* Bs[2] = { sm + 2 * STG_FLTS, sm + 3 * STG_FLTS };

    int tid  = threadIdx.x;
    int warp = tid >> 5;
    int lane = tid & 31;
    int wm = warp >> 2;           // 0..1
    int wn = warp & 3;            // 0..3
    int n0b = blockIdx.x;         // 0..3
    int m0b = blockIdx.y;         // 0..781
    int gq = lane >> 2;           // 0..7
    int gr = lane & 3;            // 0..3

    const float* Atiles = Ap + (size_t)m0b * K_TILES * 4096;
    const float* Btiles = Bp + (size_t)n0b * K_TILES * 4096;

    float acc[4][4][4];
    #pragma unroll
    for (int i = 0; i < 4; i++)
        #pragma unroll
        for (int j = 0; j < 4; j++)
            #pragma unroll
            for (int r = 0; r < 4; r++) acc[i][j][r] = 0.0f;

    auto load_stage = [&](int kt, int buf) {
        #pragma unroll
        for (int j = 0; j < 4; j++) {
            int slot = tid + 256 * j;           // 0..1023 (16B chunks)
            int ch = slot >> 6, inner = slot & 63;
            int smoff = ch * CH_STRIDE + inner * 4;
            cp16(smem_u32(&As[buf][smoff]), Atiles + (size_t)kt * 4096 + slot * 4);
            cp16(smem_u32(&Bs[buf][smoff]), Btiles + (size_t)kt * 4096 + slot * 4);
        }
        asm volatile("cp.async.commit_group;");
    };

    load_stage(0, 0);

    for (int it = 0; it < K_TILES; it++) {
        asm volatile("cp.async.wait_group 0;");
        __syncthreads();
        if (it + 1 < K_TILES) load_stage(it + 1, (it + 1) & 1);

        const float* Ab = As[it & 1];
        const float* Bb = Bs[it & 1];
        #pragma unroll
        for (int s = 0; s < 4; s++) {
            int choff = (s * 4 + gr) * CH_STRIDE;
            float af[4][4], bf[4][2];
            #pragma unroll
            for (int mf = 0; mf < 4; mf++) {
                float4 aq = *(const float4*)&Ab[choff + ((wm * 4 + mf) * 8 + gq) * 4];
                af[mf][0] = aq.x; af[mf][1] = aq.y; af[mf][2] = aq.z; af[mf][3] = aq.w;
            }
            #pragma unroll
            for (int nfp = 0; nfp < 2; nfp++) {
                float4 bq = *(const float4*)&Bb[choff + ((wn * 2 + nfp) * 8 + gq) * 4];
                bf[2 * nfp][0]     = bq.x; bf[2 * nfp][1]     = bq.y;
                bf[2 * nfp + 1][0] = bq.z; bf[2 * nfp + 1][1] = bq.w;
            }
            #pragma unroll
            for (int mf = 0; mf < 4; mf++)
                #pragma unroll
                for (int nf = 0; nf < 4; nf++)
                    mma_tf32(acc[mf][nf], af[mf], bf[nf]);
        }
        __syncthreads();
    }

    // epilogue (C normal row-major layout)
    #pragma unroll
    for (int mf = 0; mf < 4; mf++) {
        int r0 = m0b * 128 + wm * 64 + mf * 16 + gq;
        #pragma unroll
        for (int nf = 0; nf < 4; nf++) {
            int cN = n0b * 128 + wn * 32 + nf * 8 + gr * 2;
            float b0 = ADD_BIAS ? bias[cN]     : 0.0f;
            float b1 = ADD_BIAS ? bias[cN + 1] : 0.0f;
            if (r0 < M)
                *(float2*)(C + (size_t)r0 * N_GENES + cN) =
                    make_float2(acc[mf][nf][0] + b0, acc[mf][nf][1] + b1);
            if (r0 + 8 < M)
                *(float2*)(C + (size_t)(r0 + 8) * N_GENES + cN) =
                    make_float2(acc[mf][nf][2] + b0, acc[mf][nf][3] + b1);
        }
    }
}

// ---------------- CSR build: count, scan, bucket ----------------------------
__global__ void k_cnt(const int* __restrict__ dst) {
    int e = blockIdx.x * blockDim.x + threadIdx.x;
    if (e < N_EDGES) atomicAdd(&g_cnt[dst[e]], 1);
}

__global__ void k_scan1(void) {
    __shared__ int s[1024];
    int t = threadIdx.x;
    int i = blockIdx.x * 1024 + t;
    int v = (i < N_SPOTS) ? g_cnt[i] : 0;
    s[t] = v;
    __syncthreads();
    for (int off = 1; off < 1024; off <<= 1) {
        int a = (t >= off) ? s[t - off] : 0;
        __syncthreads();
        s[t] += a;
        __syncthreads();
    }
    if (i < N_SPOTS) g_off[i] = s[t] - v;
    if (t == 1023) g_bsum[blockIdx.x] = s[1023];
}

__global__ void k_scan2(void) {
    __shared__ int s[128];
    int t = threadIdx.x;
    int v = (t < SCAN_B) ? g_bsum[t] : 0;
    s[t] = v;
    __syncthreads();
    for (int off = 1; off < 128; off <<= 1) {
        int a = (t >= off) ? s[t - off] : 0;
        __syncthreads();
        s[t] += a;
        __syncthreads();
    }
    if (t < SCAN_B) g_bsum[t] = s[t] - v;
}

__global__ void k_scan3(void) {
    int i = blockIdx.x * blockDim.x + threadIdx.x;
    if (i < N_SPOTS) {
        int off = g_off[i] + g_bsum[i >> 10];
        g_off[i] = off;
        g_cur[i] = off;
        int c = g_cnt[i];
        g_dinv[i] = (c > 0) ? rsqrtf((float)c) : 0.0f;
    }
    if (i == 0) g_off[N_SPOTS] = N_EDGES;
}

__global__ void k_bucket(const int* __restrict__ src, const int* __restrict__ dst) {
    int e = blockIdx.x * blockDim.x + threadIdx.x;
    if (e < N_EDGES) {
        int pos = atomicAdd(&g_cur[dst[e]], 1);
        g_ebuf[pos] = src[e];
    }
}

// ---------------- gather: msg[d] = bc + sum_{src in bucket(d)} norm * x[src]
__global__ void k_gather(const float* __restrict__ bc, float* __restrict__ msg) {
    int d = blockIdx.x;
    int t = threadIdx.x;            // 0..127
    int beg = g_off[d], end = g_off[d + 1];
    float di = g_dinv[d];
    float4 acc = ((const float4*)bc)[t];
    for (int i = beg; i < end; i++) {
        int s = g_ebuf[i];
        float nrm = di * g_dinv[s];
        float4 v = ((const float4*)(g_x + (size_t)s * N_GENES))[t];
        acc.x = fmaf(nrm, v.x, acc.x);
        acc.y = fmaf(nrm, v.y, acc.y);
        acc.z = fmaf(nrm, v.z, acc.z);
        acc.w = fmaf(nrm, v.w, acc.w);
    }
    ((float4*)(msg + (size_t)d * N_GENES))[t] = acc;
}

// ---------------- mean-field scalar ----------------------------------------
__global__ void k_finalize(const float* __restrict__ Wc, const float* __restrict__ Wl,
                           float* __restrict__ out_scalar) {
    __shared__ float mean[N_GENES];
    __shared__ float red[N_GENES];
    int t = threadIdx.x;   // 512 threads
    mean[t] = g_colsum[t] * (1.0f / (float)N_SPOTS);
    __syncthreads();

    float v = 0.0f, u = 0.0f;
    const float* wc = Wc + (size_t)t * N_GENES;
    const float* wl = Wl + (size_t)t * N_GENES;
    for (int k = 0; k < N_GENES; k++) {
        float m = mean[k];
        v = fmaf((float)N_NEI * wc[k] + 2.0f * wl[k], m, v);
        u = fmaf(wl[k] + 0.5f * (float)N_NEI * wc[k], m, u);
    }

    red[t] = v * v;
    __syncthreads();
    for (int s = 256; s > 0; s >>= 1) {
        if (t < s) red[t] += red[t + s];
        __syncthreads();
    }
    float g2 = red[0];
    __syncthreads();

    red[t] = mean[t] * u;
    __syncthreads();
    for (int s = 256; s > 0; s >>= 1) {
        if (t < s) red[t] += red[t + s];
        __syncthreads();
    }
    if (t == 0) {
        float g = sqrtf(g2);
        float z_mean = -(float)N_SPOTS * red[0];
        float gc = fminf(g, 20.0f);
        float z_int;
        if (g > 20.0f)
            z_int = (float)N_SPOTS * (g - logf(g));
        else
            z_int = (float)N_SPOTS * logf((expf(gc) - expf(-gc)) / gc);
        out_scalar[0] = z_mean + z_int;
    }
}

// ---------------- launch ----------------------------------------------------
extern "C" void kernel_launch(void* const* d_in, const int* in_sizes, int n_in,
                              void* d_out, int out_size) {
    const float* sphex = (const float*)d_in[0];   // [100000, 511]
    const float* Wc    = (const float*)d_in[1];   // [512, 512]
    const float* bc    = (const float*)d_in[2];   // [512]
    const float* Wl    = (const float*)d_in[3];   // [512, 512]
    const float* bl    = (const float*)d_in[4];   // [512]
    const int*   eidx  = (const int*)d_in[5];     // [2, 600000]
    (void)in_sizes; (void)n_in; (void)out_size;

    const int* e_src = eidx;
    const int* e_dst = eidx + N_EDGES;

    float* out       = (float*)d_out;
    float* out_msg   = out;                                  // [N, G]
    float* out_intra = out + (size_t)N_SPOTS * N_GENES;      // [N, G]
    float* out_logz  = out + 2 * (size_t)N_SPOTS * N_GENES;  // [1]

    float *p_gexp, *p_x, *p_wc, *p_wl;
    cudaGetSymbolAddress((void**)&p_gexp, g_gexp);
    cudaGetSymbolAddress((void**)&p_x,    g_x);
    cudaGetSymbolAddress((void**)&p_wc,   g_wc);
    cudaGetSymbolAddress((void**)&p_wl,   g_wl);

    // 0) zero counters + pre-round/permute weights
    k_zero<<<(N_SPOTS + 255) / 256, 256>>>();
    k_cvtW<<<(N_GENES * N_GENES) / 256, 256>>>(Wc, Wl);

    // 1) CSR build (independent of gex/GEMM)
    k_cnt<<<(N_EDGES + 255) / 256, 256>>>(e_dst);
    k_scan1<<<SCAN_B, 1024>>>();
    k_scan2<<<1, 128>>>();
    k_scan3<<<(N_SPOTS + 255) / 256, 256>>>();
    k_bucket<<<(N_EDGES + 255) / 256, 256>>>(e_src, e_dst);

    // 2) gex (block per 128-row tile, permuted output + fused colsum)
    k_gex<<<M_TILES, 256>>>(sphex);

    // 3) split GEMMs (tf32 tensor cores, permuted operands, cp.async)
    {
        const int smem_bytes = 4 * STG_FLTS * sizeof(float);  // 67584
        cudaFuncSetAttribute(k_mma_gemm<false>,
                             cudaFuncAttributeMaxDynamicSharedMemorySize, smem_bytes);
        cudaFuncSetAttribute(k_mma_gemm<true>,
                             cudaFuncAttributeMaxDynamicSharedMemorySize, smem_bytes);
        dim3 grid(4, M_TILES);
        k_mma_gemm<false><<<grid, 256, smem_bytes>>>(p_gexp, p_wc, nullptr, p_x, N_SPOTS);
        k_mma_gemm<true ><<<grid, 256, smem_bytes>>>(p_gexp, p_wl, bl, out_intra, N_SPOTS);
    }

    // 4) gather per destination (bias folded in, no atomics)
    k_gather<<<N_SPOTS, 128>>>(bc, out_msg);

    // 5) mean-field scalar (colsum already accumulated by k_gex)
    k_finalize<<<1, 512>>>(Wc, Wl, out_logz);
}

// round 17
// speedup vs baseline: 1.7050x; 1.0031x over previous
#include <cuda_runtime.h>
#include <cuda_bf16.h>
#include <math.h>
#include <stdint.h>

// Problem constants (fixed by the dataset)
#define N_SPOTS   100000
#define N_GENES   512
#define N_SPH     511
#define N_EDGES   600000
#define N_NEI     6
#define SCAN_B    ((N_SPOTS + 1023) / 1024)   // 98
#define M_TILES   782                          // ceil(100000/128)
#define K_TILES   16                           // 512/32

// Permuted-layout sizes: tile = 128 rows x 32 k = 4096 floats
// A_perm: [m_tile][k_tile][chunk(16)][pos(256)]
__device__ float g_gexp[(size_t)M_TILES * K_TILES * 4096];  // 205 MB (tf32, padded)
__device__ float g_x  [(size_t)N_SPOTS * N_GENES];          // 204.8 MB
__device__ float g_wc [4 * K_TILES * 4096];                 // permuted tf32 Wc
__device__ float g_wl [4 * K_TILES * 4096];                 // permuted tf32 Wl
__device__ int   g_cnt[N_SPOTS];
__device__ int   g_off[N_SPOTS + 1];
__device__ int   g_cur[N_SPOTS];
__device__ int   g_ebuf[N_EDGES];
__device__ int   g_bsum[SCAN_B];
__device__ float g_dinv[N_SPOTS];
__device__ float g_colsum[N_GENES];

__device__ __forceinline__ float to_tf32(float x) {
    float r;
    asm("cvt.rna.tf32.f32 %0, %1;" : "=f"(r) : "f"(x));
    return r;
}

// ---------------- init ------------------------------------------------------
__global__ void k_zero(void) {
    int i = blockIdx.x * blockDim.x + threadIdx.x;
    if (i < N_SPOTS) g_cnt[i] = 0;
    if (i < N_GENES) g_colsum[i] = 0.0f;
}

// ---------------- weight pre-round to tf32, permuted B layout ----------------
// B quad per thread: [(cn,k0),(cn,k1),(cn+8,k0),(cn+8,k1)]
__global__ void k_cvtW(const float* __restrict__ Wc, const float* __restrict__ Wl) {
    int i = blockIdx.x * blockDim.x + threadIdx.x;   // 262144
    int n = i >> 9;          // W row = output col (0..511)
    int k = i & 511;
    int n0b = n >> 7, nl = n & 127;
    int kt  = k >> 5, kl = k & 31;
    int cb = nl >> 4, gq = nl & 7, e = (nl >> 3) & 1;
    int s  = kl >> 3, gr = kl & 3, h = (kl >> 2) & 1;
    size_t idx = ((size_t)(n0b * K_TILES + kt) * 16 + (s * 4 + gr)) * 256
               + (cb * 8 + gq) * 4 + (2 * e + h);
    g_wc[idx] = to_tf32(Wc[i]);
    g_wl[idx] = to_tf32(Wl[i]);
}

// ---------------- gex: block per 128-row tile, permuted output + colsum -----
// A quad per thread: [(q,k0),(q+8,k0),(q,k1),(q+8,k1)]
#define GEX_STRIDE 260     // staging chunk stride (floats)
__global__ void __launch_bounds__(256)
k_gex(const float* __restrict__ sphex) {
    __shared__ float sbuf[16 * GEX_STRIDE];  // one permuted 128x32 chunk
    __shared__ float scol[N_GENES];

    int tid  = threadIdx.x;
    int warp = tid >> 5;          // 0..7 -> 16-row block mb = warp
    int lane = tid & 31;
    int blk  = blockIdx.x;        // 0..781

    scol[tid] = 0.0f; scol[tid + 256] = 0.0f;
    __syncthreads();

    // per-lane copy of running sin-products for this warp's 16 rows
    float P[16];
    #pragma unroll
    for (int r = 0; r < 16; r++) P[r] = 1.0f;

    int s4 = lane >> 3, gr = lane & 3, h = (lane >> 2) & 1;
    int chunk = s4 * 4 + gr;

    for (int kc = 0; kc < K_TILES; kc++) {
        int col = kc * 32 + lane;
        float csum = 0.0f;
        #pragma unroll
        for (int rr = 0; rr < 16; rr++) {
            int row = blk * 128 + warp * 16 + rr;
            bool vrow = row < N_SPOTS;
            float sv = 1.0f, cv = 1.0f;
            if (vrow && col < N_SPH) {
                float xv = sphex[(size_t)row * N_SPH + col];
                sincosf(xv, &sv, &cv);
            }
            // inclusive warp product scan
            float incl = sv;
            #pragma unroll
            for (int off = 1; off < 32; off <<= 1) {
                float o = __shfl_up_sync(0xffffffffu, incl, off);
                if (lane >= off) incl *= o;
            }
            float excl = __shfl_up_sync(0xffffffffu, incl, 1);
            if (lane == 0) excl = 1.0f;
            float out = vrow ? to_tf32(P[rr] * excl * cv) : 0.0f;
            P[rr] *= __shfl_sync(0xffffffffu, incl, 31);
            csum += out;
            int q = rr & 7, p = rr >> 3;
            sbuf[chunk * GEX_STRIDE + (warp * 8 + q) * 4 + (p + 2 * h)] = out;
        }
        atomicAdd(&scol[kc * 32 + lane], csum);
        __syncthreads();
        // coalesced permuted store of this 128x32 tile
        float* dstt = g_gexp + (size_t)(blk * K_TILES + kc) * 4096;
        #pragma unroll
        for (int jj = 0; jj < 4; jj++) {
            int i = tid + 256 * jj;       // float4 slot 0..1023
            int gpos = i * 4;
            int ch = gpos >> 8, pos = gpos & 255;
            float4 v = *(const float4*)&sbuf[ch * GEX_STRIDE + pos];
            *(float4*)(dstt + gpos) = v;
        }
        __syncthreads();
    }
    atomicAdd(&g_colsum[tid],       scol[tid]);
    atomicAdd(&g_colsum[tid + 256], scol[tid + 256]);
}

// ---------------- TF32 tensor GEMM, permuted operands, cp.async 2-stage -----
#define CH_STRIDE 264      // smem chunk stride (floats): 16B-units ≡ 2 mod 8
#define STG_FLTS  (16 * CH_STRIDE)   // 4224 floats per matrix per stage

__device__ __forceinline__ uint32_t smem_u32(const void* p) {
    return (uint32_t)__cvta_generic_to_shared(p);
}
__device__ __forceinline__ void cp16(uint32_t dst, const void* src) {
    asm volatile("cp.async.ca.shared.global [%0], [%1], 16;"
                 :: "r"(dst), "l"(src));
}

__device__ __forceinline__ void mma_tf32(float* c, const float* a, const float* b) {
    const uint32_t* A = reinterpret_cast<const uint32_t*>(a);
    const uint32_t* B = reinterpret_cast<const uint32_t*>(b);
    asm volatile(
        "mma.sync.aligned.m16n8k8.row.col.f32.tf32.tf32.f32 "
        "{%0,%1,%2,%3}, {%4,%5,%6,%7}, {%8,%9}, {%0,%1,%2,%3};"
        : "+f"(c[0]), "+f"(c[1]), "+f"(c[2]), "+f"(c[3])
        : "r"(A[0]), "r"(A[1]), "r"(A[2]), "r"(A[3]), "r"(B[0]), "r"(B[1]));
}

template <bool ADD_BIAS>
__global__ void __launch_bounds__(256, 2)
k_mma_gemm(const float* __restrict__ Ap, const float* __restrict__ Bp,
           const float* __restrict__ bias, float* __restrict__ C, int M) {
    extern __shared__ float sm[];
    float* As[2] = { sm,                sm + STG_FLTS };
    float* Bs[2] = { sm + 2 * STG_FLTS, sm + 3 * STG_FLTS };

    int tid  = threadIdx.x;
    int warp = tid >> 5;
    int lane = tid & 31;
    int wm = warp >> 2;           // 0..1
    int wn = warp & 3;            // 0..3
    int n0b = blockIdx.x;         // 0..3
    int m0b = blockIdx.y;         // 0..781
    int gq = lane >> 2;           // 0..7
    int gr = lane & 3;            // 0..3

    const float* Atiles = Ap + (size_t)m0b * K_TILES * 4096;
    const float* Btiles = Bp + (size_t)n0b * K_TILES * 4096;

    float acc[4][4][4];
    #pragma unroll
    for (int i = 0; i < 4; i++)
        #pragma unroll
        for (int j = 0; j < 4; j++)
            #pragma unroll
            for (int r = 0; r < 4; r++) acc[i][j][r] = 0.0f;

    auto load_stage = [&](int kt, int buf) {
        #pragma unroll
        for (int j = 0; j < 4; j++) {
            int slot = tid + 256 * j;           // 0..1023 (16B chunks)
            int ch = slot >> 6, inner = slot & 63;
            int smoff = ch * CH_STRIDE + inner * 4;
            cp16(smem_u32(&As[buf][smoff]), Atiles + (size_t)kt * 4096 + slot * 4);
            cp16(smem_u32(&Bs[buf][smoff]), Btiles + (size_t)kt * 4096 + slot * 4);
        }
        asm volatile("cp.async.commit_group;");
    };

    load_stage(0, 0);

    for (int it = 0; it < K_TILES; it++) {
        asm volatile("cp.async.wait_group 0;");
        __syncthreads();
        if (it + 1 < K_TILES) load_stage(it + 1, (it + 1) & 1);

        const float* Ab = As[it & 1];
        const float* Bb = Bs[it & 1];
        #pragma unroll
        for (int s = 0; s < 4; s++) {
            int choff = (s * 4 + gr) * CH_STRIDE;
            float af[4][4], bf[4][2];
            #pragma unroll
            for (int mf = 0; mf < 4; mf++) {
                float4 aq = *(const float4*)&Ab[choff + ((wm * 4 + mf) * 8 + gq) * 4];
                af[mf][0] = aq.x; af[mf][1] = aq.y; af[mf][2] = aq.z; af[mf][3] = aq.w;
            }
            #pragma unroll
            for (int nfp = 0; nfp < 2; nfp++) {
                float4 bq = *(const float4*)&Bb[choff + ((wn * 2 + nfp) * 8 + gq) * 4];
                bf[2 * nfp][0]     = bq.x; bf[2 * nfp][1]     = bq.y;
                bf[2 * nfp + 1][0] = bq.z; bf[2 * nfp + 1][1] = bq.w;
            }
            #pragma unroll
            for (int mf = 0; mf < 4; mf++)
                #pragma unroll
                for (int nf = 0; nf < 4; nf++)
                    mma_tf32(acc[mf][nf], af[mf], bf[nf]);
        }
        __syncthreads();
    }

    // epilogue (C normal row-major layout)
    #pragma unroll
    for (int mf = 0; mf < 4; mf++) {
        int r0 = m0b * 128 + wm * 64 + mf * 16 + gq;
        #pragma unroll
        for (int nf = 0; nf < 4; nf++) {
            int cN = n0b * 128 + wn * 32 + nf * 8 + gr * 2;
            float b0 = ADD_BIAS ? bias[cN]     : 0.0f;
            float b1 = ADD_BIAS ? bias[cN + 1] : 0.0f;
            if (r0 < M)
                *(float2*)(C + (size_t)r0 * N_GENES + cN) =
                    make_float2(acc[mf][nf][0] + b0, acc[mf][nf][1] + b1);
            if (r0 + 8 < M)
                *(float2*)(C + (size_t)(r0 + 8) * N_GENES + cN) =
                    make_float2(acc[mf][nf][2] + b0, acc[mf][nf][3] + b1);
        }
    }
}

// ---------------- CSR build: count, scan, bucket ----------------------------
__global__ void k_cnt(const int* __restrict__ dst) {
    int e = blockIdx.x * blockDim.x + threadIdx.x;
    if (e < N_EDGES) atomicAdd(&g_cnt[dst[e]], 1);
}

__global__ void k_scan1(void) {
    __shared__ int s[1024];
    int t = threadIdx.x;
    int i = blockIdx.x * 1024 + t;
    int v = (i < N_SPOTS) ? g_cnt[i] : 0;
    s[t] = v;
    __syncthreads();
    for (int off = 1; off < 1024; off <<= 1) {
        int a = (t >= off) ? s[t - off] : 0;
        __syncthreads();
        s[t] += a;
        __syncthreads();
    }
    if (i < N_SPOTS) g_off[i] = s[t] - v;
    if (t == 1023) g_bsum[blockIdx.x] = s[1023];
}

__global__ void k_scan2(void) {
    __shared__ int s[128];
    int t = threadIdx.x;
    int v = (t < SCAN_B) ? g_bsum[t] : 0;
    s[t] = v;
    __syncthreads();
    for (int off = 1; off < 128; off <<= 1) {
        int a = (t >= off) ? s[t - off] : 0;
        __syncthreads();
        s[t] += a;
        __syncthreads();
    }
    if (t < SCAN_B) g_bsum[t] = s[t] - v;
}

__global__ void k_scan3(void) {
    int i = blockIdx.x * blockDim.x + threadIdx.x;
    if (i < N_SPOTS) {
        int off = g_off[i] + g_bsum[i >> 10];
        g_off[i] = off;
        g_cur[i] = off;
        int c = g_cnt[i];
        g_dinv[i] = (c > 0) ? rsqrtf((float)c) : 0.0f;
    }
    if (i == 0) g_off[N_SPOTS] = N_EDGES;
}

__global__ void k_bucket(const int* __restrict__ src, const int* __restrict__ dst) {
    int e = blockIdx.x * blockDim.x + threadIdx.x;
    if (e < N_EDGES) {
        int pos = atomicAdd(&g_cur[dst[e]], 1);
        g_ebuf[pos] = src[e];
    }
}

// ---------------- gather: msg[d] = bc + sum_{src in bucket(d)} norm * x[src]
__global__ void k_gather(const float* __restrict__ bc, float* __restrict__ msg) {
    int d = blockIdx.x;
    int t = threadIdx.x;            // 0..127
    int beg = g_off[d], end = g_off[d + 1];
    float di = g_dinv[d];
    float4 acc = ((const float4*)bc)[t];
    for (int i = beg; i < end; i++) {
        int s = g_ebuf[i];
        float nrm = di * g_dinv[s];
        float4 v = ((const float4*)(g_x + (size_t)s * N_GENES))[t];
        acc.x = fmaf(nrm, v.x, acc.x);
        acc.y = fmaf(nrm, v.y, acc.y);
        acc.z = fmaf(nrm, v.z, acc.z);
        acc.w = fmaf(nrm, v.w, acc.w);
    }
    ((float4*)(msg + (size_t)d * N_GENES))[t] = acc;
}

// ---------------- mean-field scalar ----------------------------------------
__global__ void k_finalize(const float* __restrict__ Wc, const float* __restrict__ Wl,
                           float* __restrict__ out_scalar) {
    __shared__ float mean[N_GENES];
    __shared__ float red[N_GENES];
    int t = threadIdx.x;   // 512 threads
    mean[t] = g_colsum[t] * (1.0f / (float)N_SPOTS);
    __syncthreads();

    float v = 0.0f, u = 0.0f;
    const float* wc = Wc + (size_t)t * N_GENES;
    const float* wl = Wl + (size_t)t * N_GENES;
    for (int k = 0; k < N_GENES; k++) {
        float m = mean[k];
        v = fmaf((float)N_NEI * wc[k] + 2.0f * wl[k], m, v);
        u = fmaf(wl[k] + 0.5f * (float)N_NEI * wc[k], m, u);
    }

    red[t] = v * v;
    __syncthreads();
    for (int s = 256; s > 0; s >>= 1) {
        if (t < s) red[t] += red[t + s];
        __syncthreads();
    }
    float g2 = red[0];
    __syncthreads();

    red[t] = mean[t] * u;
    __syncthreads();
    for (int s = 256; s > 0; s >>= 1) {
        if (t < s) red[t] += red[t + s];
        __syncthreads();
    }
    if (t == 0) {
        float g = sqrtf(g2);
        float z_mean = -(float)N_SPOTS * red[0];
        float gc = fminf(g, 20.0f);
        float z_int;
        if (g > 20.0f)
            z_int = (float)N_SPOTS * (g - logf(g));
        else
            z_int = (float)N_SPOTS * logf((expf(gc) - expf(-gc)) / gc);
        out_scalar[0] = z_mean + z_int;
    }
}

// ---------------- launch ----------------------------------------------------
extern "C" void kernel_launch(void* const* d_in, const int* in_sizes, int n_in,
                              void* d_out, int out_size) {
    const float* sphex = (const float*)d_in[0];   // [100000, 511]
    const float* Wc    = (const float*)d_in[1];   // [512, 512]
    const float* bc    = (const float*)d_in[2];   // [512]
    const float* Wl    = (const float*)d_in[3];   // [512, 512]
    const float* bl    = (const float*)d_in[4];   // [512]
    const int*   eidx  = (const int*)d_in[5];     // [2, 600000]
    (void)in_sizes; (void)n_in; (void)out_size;

    const int* e_src = eidx;
    const int* e_dst = eidx + N_EDGES;

    float* out       = (float*)d_out;
    float* out_msg   = out;                                  // [N, G]
    float* out_intra = out + (size_t)N_SPOTS * N_GENES;      // [N, G]
    float* out_logz  = out + 2 * (size_t)N_SPOTS * N_GENES;  // [1]

    float *p_gexp, *p_x, *p_wc, *p_wl;
    cudaGetSymbolAddress((void**)&p_gexp, g_gexp);
    cudaGetSymbolAddress((void**)&p_x,    g_x);
    cudaGetSymbolAddress((void**)&p_wc,   g_wc);
    cudaGetSymbolAddress((void**)&p_wl,   g_wl);

    // 0) zero counters + pre-round/permute weights
    k_zero<<<(N_SPOTS + 255) / 256, 256>>>();
    k_cvtW<<<(N_GENES * N_GENES) / 256, 256>>>(Wc, Wl);

    // 1) CSR build (independent of gex/GEMM)
    k_cnt<<<(N_EDGES + 255) / 256, 256>>>(e_dst);
    k_scan1<<<SCAN_B, 1024>>>();
    k_scan2<<<1, 128>>>();
    k_scan3<<<(N_SPOTS + 255) / 256, 256>>>();
    k_bucket<<<(N_EDGES + 255) / 256, 256>>>(e_src, e_dst);

    // 2) gex (block per 128-row tile, permuted output + fused colsum)
    k_gex<<<M_TILES, 256>>>(sphex);

    // 3) split GEMMs (tf32 tensor cores, permuted operands, cp.async)
    {
        const int smem_bytes = 4 * STG_FLTS * sizeof(float);  // 67584
        cudaFuncSetAttribute(k_mma_gemm<false>,
                             cudaFuncAttributeMaxDynamicSharedMemorySize, smem_bytes);
        cudaFuncSetAttribute(k_mma_gemm<true>,
                             cudaFuncAttributeMaxDynamicSharedMemorySize, smem_bytes);
        dim3 grid(4, M_TILES);
        k_mma_gemm<false><<<grid, 256, smem_bytes>>>(p_gexp, p_wc, nullptr, p_x, N_SPOTS);
        k_mma_gemm<true ><<<grid, 256, smem_bytes>>>(p_gexp, p_wl, bl, out_intra, N_SPOTS);
    }

    // 4) gather per destination (bias folded in, no atomics)
    k_gather<<<N_SPOTS, 128>>>(bc, out_msg);

    // 5) mean-field scalar (colsum already accumulated by k_gex)
    k_finalize<<<1, 512>>>(Wc, Wl, out_logz);
}